// round 8
// baseline (speedup 1.0000x reference)
#include <cuda_runtime.h>
#include <math.h>
#include <stdint.h>

#define NL 8
#define NS 192
#define ND 512
#define NF 2048
#define NB 16
#define EPSF 1e-5f

// ---------------- scratch (static device globals; no allocations) ----------------
__device__ uint2 d_qfs  [NB*NL*ND*NS];        // split q_feat  [b][i*D+d][t]
__device__ uint2 d_gfs  [NB*NL*ND*NS];        // split g_feat
__device__ uint2 d_w0s  [NL*ND*ND];           // split fc0_w   [i][e][d]
__device__ uint2 d_query2[NL*NB*NS*ND];       // split query   [i][b][t][e]
__device__ uint2 d_key2  [NL*NB*NS*ND];       // split key     [i][b][s][e]
__device__ float d_sigse[NL*NS*NS];           // sigmoid(score_embed)
__device__ float d_x    [NL*512*NS];          // [i][r=2qk+branch][S]
__device__ float d_colp [NL*256*6*NS];        // per-t-tile colmax partials
__device__ float d_bn1m[NL], d_bn1r[NL];
__device__ float d_u    [NL*512*NF];          // fc2 output
__device__ float d_bn2m[NL*NF], d_bn2r[NL*NF];
__device__ float d_y    [NL*512];             // fc3 per-row output

// ---------------- tf32 helpers ----------------
__device__ __forceinline__ uint32_t f2tf32(float x){
    uint32_t r; asm("cvt.rna.tf32.f32 %0, %1;" : "=r"(r) : "f"(x)); return r;
}
__device__ __forceinline__ uint2 tf32_split(float x){
    uint32_t hi = f2tf32(x);
    uint32_t lo = f2tf32(x - __uint_as_float(hi));
    return make_uint2(hi, lo);
}
__device__ __forceinline__ void mma_tf32(float* c, const uint32_t* a, const uint32_t* b){
    asm volatile("mma.sync.aligned.m16n8k8.row.col.f32.tf32.tf32.f32 "
        "{%0,%1,%2,%3}, {%4,%5,%6,%7}, {%8,%9}, {%0,%1,%2,%3};"
        : "+f"(c[0]),"+f"(c[1]),"+f"(c[2]),"+f"(c[3])
        : "r"(a[0]),"r"(a[1]),"r"(a[2]),"r"(a[3]), "r"(b[0]),"r"(b[1]));
}
// 3 mma: aH*bH + aH*bL + aL*bH
__device__ __forceinline__ void mma3(float* acc, const uint2* ap, const uint2* bp){
    uint32_t aH[4] = {ap[0].x, ap[1].x, ap[2].x, ap[3].x};
    uint32_t aL[4] = {ap[0].y, ap[1].y, ap[2].y, ap[3].y};
    uint32_t bH[2] = {bp[0].x, bp[1].x};
    uint32_t bL[2] = {bp[0].y, bp[1].y};
    mma_tf32(acc, aL, bH);
    mma_tf32(acc, aH, bL);
    mma_tf32(acc, aH, bH);
}

// ---------------- elementwise tf32 split ----------------
__global__ void k_split(const float* __restrict__ src, uint2* __restrict__ dst, int n){
    int idx = blockIdx.x*256 + threadIdx.x;
    if (idx < n) dst[idx] = tf32_split(src[idx]);
}

// ---------------- precompute sigmoid(score_embed) ----------------
__global__ void k_sigse(const float* __restrict__ se){
    int idx = blockIdx.x*256 + threadIdx.x;
    if (idx < NL*NS*NS) d_sigse[idx] = 1.f/(1.f+expf(-se[idx]));
}

// ---------------- fc0 projection (3xTF32 mma, split inputs, split output)
// out[i][b][t][e] = sum_d feat[b][i*D+d][t] * w0[i][e][d] + b0[i][e]
// grid (16 e-tiles, B, L), 128 threads (4 warps). CTA: 192 t x 32 e, K=512 in kc=16.
__global__ void __launch_bounds__(128) k_proj(const uint2* __restrict__ featS,
                       const float* __restrict__ b0, uint2* __restrict__ outS){
    const int i = blockIdx.z, b = blockIdx.y, e0 = blockIdx.x*32;
    const int tid = threadIdx.x;
    const int w = tid>>5, lane = tid&31;
    const int g = lane>>2, c = lane&3;
    __shared__ uint2 As2[16*193];   // [kk][t], pad 193
    __shared__ uint2 Bs2[32*17];    // [e][kk]
    float acc[3][4][4];
#pragma unroll
    for (int mt=0;mt<3;mt++)
#pragma unroll
        for (int nt=0;nt<4;nt++)
#pragma unroll
            for (int r=0;r<4;r++) acc[mt][nt][r]=0.f;
    const uint2* fbase = featS + (size_t)(b*(ND*NL) + i*ND)*NS;
    const uint2* wbase = d_w0s + (size_t)i*ND*ND + (size_t)e0*ND;
    const int tb = w*48;
    for (int kc = 0; kc < ND; kc += 16){
        for (int idx = tid; idx < 16*NS; idx += 128){
            int kk = idx / NS, t = idx - kk*NS;
            As2[kk*193 + t] = fbase[(size_t)(kc+kk)*NS + t];
        }
        for (int idx = tid; idx < 32*16; idx += 128){
            int ee = idx >> 4, kk = idx & 15;
            Bs2[ee*17 + kk] = wbase[(size_t)ee*ND + kc + kk];
        }
        __syncthreads();
#pragma unroll
        for (int ks=0; ks<2; ks++){
            const int k0 = ks*8;
            uint2 bp[4][2];
#pragma unroll
            for (int nt=0;nt<4;nt++){
                int e = nt*8 + g;
                bp[nt][0] = Bs2[e*17 + k0 + c];
                bp[nt][1] = Bs2[e*17 + k0 + 4 + c];
            }
#pragma unroll
            for (int mt=0;mt<3;mt++){
                int r = tb + mt*16 + g;
                uint2 ap[4];
                ap[0] = As2[(k0+c)*193 + r];
                ap[1] = As2[(k0+c)*193 + r + 8];
                ap[2] = As2[(k0+4+c)*193 + r];
                ap[3] = As2[(k0+4+c)*193 + r + 8];
#pragma unroll
                for (int nt=0;nt<4;nt++) mma3(acc[mt][nt], ap, bp[nt]);
            }
        }
        __syncthreads();
    }
    // epilogue: + bias, split, store uint4 (two uint2 elements)
    uint2* obase = outS + (size_t)(i*NB+b)*NS*ND;
#pragma unroll
    for (int nt=0;nt<4;nt++){
        int e = e0 + nt*8 + 2*c;
        float b01 = b0[i*ND + e], b11 = b0[i*ND + e + 1];
#pragma unroll
        for (int mt=0;mt<3;mt++){
            int r = tb + mt*16 + g;
            uint2 s00 = tf32_split(acc[mt][nt][0] + b01);
            uint2 s01 = tf32_split(acc[mt][nt][1] + b11);
            uint2 s10 = tf32_split(acc[mt][nt][2] + b01);
            uint2 s11 = tf32_split(acc[mt][nt][3] + b11);
            *reinterpret_cast<uint4*>(&obase[(size_t)r*ND + e])     = make_uint4(s00.x,s00.y,s01.x,s01.y);
            *reinterpret_cast<uint4*>(&obase[(size_t)(r+8)*ND + e]) = make_uint4(s10.x,s10.y,s11.x,s11.y);
        }
    }
}

// ---------------- score GEMM (3xTF32, split inputs) + mask + max pooling
// grid (6 t-tiles, 256 qk, L), 128 threads (4 warps). CTA: s=192 x t=32, K=512 kc=16.
__global__ void __launch_bounds__(128) k_score(){
    const int i = blockIdx.z, qk = blockIdx.y, tt = blockIdx.x;
    const int q = qk >> 4, k = qk & 15;
    const int t0 = tt*32;
    const int tid = threadIdx.x;
    const int w = tid>>5, lane = tid&31;
    const int g = lane>>2, c = lane&3;
    __shared__ uint2 As2[NS*17];    // key  [s][kk]
    __shared__ uint2 Bs2[32*17];    // query[t][kk]
    __shared__ float rowsm[4][32];
    float acc[3][4][4];
#pragma unroll
    for (int mt=0;mt<3;mt++)
#pragma unroll
        for (int nt=0;nt<4;nt++)
#pragma unroll
            for (int r=0;r<4;r++) acc[mt][nt][r]=0.f;
    const uint2* kbase = d_key2   + (size_t)(i*NB+k)*NS*ND;
    const uint2* qbase = d_query2 + (size_t)(i*NB+q)*NS*ND + (size_t)t0*ND;
    const int sb = w*48;
    for (int kc=0; kc<ND; kc+=16){
        for (int idx=tid; idx<NS*16; idx+=128){
            int s = idx>>4, kk = idx&15;
            As2[s*17 + kk] = kbase[(size_t)s*ND + kc+kk];
        }
        for (int idx=tid; idx<32*16; idx+=128){
            int tv = idx>>4, kk = idx&15;
            Bs2[tv*17 + kk] = qbase[(size_t)tv*ND + kc+kk];
        }
        __syncthreads();
#pragma unroll
        for (int ks=0; ks<2; ks++){
            const int k0 = ks*8;
            uint2 bp[4][2];
#pragma unroll
            for (int nt=0;nt<4;nt++){
                int t = nt*8 + g;
                bp[nt][0] = Bs2[t*17 + k0 + c];
                bp[nt][1] = Bs2[t*17 + k0 + 4 + c];
            }
#pragma unroll
            for (int mt=0;mt<3;mt++){
                int s = sb + mt*16 + g;
                uint2 ap[4];
                ap[0] = As2[s*17 + k0 + c];
                ap[1] = As2[(s+8)*17 + k0 + c];
                ap[2] = As2[s*17 + k0 + 4 + c];
                ap[3] = As2[(s+8)*17 + k0 + 4 + c];
#pragma unroll
                for (int nt=0;nt<4;nt++) mma3(acc[mt][nt], ap, bp[nt]);
            }
        }
        __syncthreads();
    }
    // mask by sigmoid(score_embed): acc[mt][nt][{0,1,2,3}] ~ (s0,t0),(s0,t0+1),(s0+8,t0),(s0+8,t0+1)
    const float* sbase = d_sigse + (size_t)i*NS*NS;
#pragma unroll
    for (int mt=0;mt<3;mt++){
        int r0 = sb + mt*16 + g, r1 = r0 + 8;
#pragma unroll
        for (int nt=0;nt<4;nt++){
            int tc = t0 + nt*8 + 2*c;
            acc[mt][nt][0] *= sbase[r0*NS + tc];
            acc[mt][nt][1] *= sbase[r0*NS + tc + 1];
            acc[mt][nt][2] *= sbase[r1*NS + tc];
            acc[mt][nt][3] *= sbase[r1*NS + tc + 1];
        }
    }
    // ---- rowmax: max over s (per t column) ----
    float rm[4][2];
#pragma unroll
    for (int nt=0;nt<4;nt++){
        float m0 = fmaxf(acc[0][nt][0], acc[0][nt][2]);
        float m1 = fmaxf(acc[0][nt][1], acc[0][nt][3]);
#pragma unroll
        for (int mt=1;mt<3;mt++){
            m0 = fmaxf(m0, fmaxf(acc[mt][nt][0], acc[mt][nt][2]));
            m1 = fmaxf(m1, fmaxf(acc[mt][nt][1], acc[mt][nt][3]));
        }
        rm[nt][0] = m0; rm[nt][1] = m1;
    }
#pragma unroll
    for (int off=4; off<32; off<<=1)
#pragma unroll
        for (int nt=0;nt<4;nt++){
            rm[nt][0] = fmaxf(rm[nt][0], __shfl_xor_sync(0xffffffffu, rm[nt][0], off));
            rm[nt][1] = fmaxf(rm[nt][1], __shfl_xor_sync(0xffffffffu, rm[nt][1], off));
        }
    if (lane < 4){
#pragma unroll
        for (int nt=0;nt<4;nt++){
            rowsm[w][nt*8 + 2*lane]     = rm[nt][0];
            rowsm[w][nt*8 + 2*lane + 1] = rm[nt][1];
        }
    }
    __syncthreads();
    if (tid < 32){
        float m = fmaxf(fmaxf(rowsm[0][tid], rowsm[1][tid]), fmaxf(rowsm[2][tid], rowsm[3][tid]));
        d_x[((size_t)i*512 + 2*qk)*NS + t0 + tid] = m;
    }
    // ---- colmax: max over this tile's 32 t (per s row); partial across t-tiles ----
    float cm[3][2];
#pragma unroll
    for (int mt=0;mt<3;mt++){
        float m0 = fmaxf(acc[mt][0][0], acc[mt][0][1]);
        float m1 = fmaxf(acc[mt][0][2], acc[mt][0][3]);
#pragma unroll
        for (int nt=1;nt<4;nt++){
            m0 = fmaxf(m0, fmaxf(acc[mt][nt][0], acc[mt][nt][1]));
            m1 = fmaxf(m1, fmaxf(acc[mt][nt][2], acc[mt][nt][3]));
        }
        cm[mt][0] = m0; cm[mt][1] = m1;
    }
#pragma unroll
    for (int off=1; off<4; off<<=1)
#pragma unroll
        for (int mt=0;mt<3;mt++){
            cm[mt][0] = fmaxf(cm[mt][0], __shfl_xor_sync(0xffffffffu, cm[mt][0], off));
            cm[mt][1] = fmaxf(cm[mt][1], __shfl_xor_sync(0xffffffffu, cm[mt][1], off));
        }
    if (c == 0){
        float* cpb = d_colp + ((size_t)(i*256+qk)*6 + tt)*NS;
#pragma unroll
        for (int mt=0;mt<3;mt++){
            int r = sb + mt*16 + g;
            cpb[r]     = cm[mt][0];
            cpb[r + 8] = cm[mt][1];
        }
    }
}

// ---------------- merge colmax partials (6 t-tiles) into odd rows of x
__global__ void k_colmerge(){
    int idx = blockIdx.x*256 + threadIdx.x;       // NL*256*NS = 393216
    if (idx >= NL*256*NS) return;
    int s   = idx % NS;
    int iqk = idx / NS;
    int i   = iqk >> 8;
    int qk  = iqk & 255;
    const float* p = d_colp + (size_t)iqk*6*NS + s;
    float m = p[0];
#pragma unroll
    for (int j=1;j<6;j++) m = fmaxf(m, p[(size_t)j*NS]);
    d_x[((size_t)i*512 + 2*qk + 1)*NS + s] = m;
}

// ---------------- bn1 stats (whole-tensor mean/var per layer), double accum
__global__ void k_bn1(){
    const int i = blockIdx.x, tid = threadIdx.x;   // 8 blocks x 512 threads
    const float* p = d_x + (size_t)i*512*NS;
    double s=0.0, sq=0.0;
    for (int idx=tid; idx<512*NS; idx+=512){ double v = p[idx]; s+=v; sq+=v*v; }
    __shared__ double ss[512], sqs[512];
    ss[tid]=s; sqs[tid]=sq; __syncthreads();
    for (int off=256; off; off>>=1){
        if (tid<off){ ss[tid]+=ss[tid+off]; sqs[tid]+=sqs[tid+off]; }
        __syncthreads();
    }
    if (tid==0){
        double n = 512.0*NS;
        double mean = ss[0]/n;
        double var  = sqs[0]/n - mean*mean;
        d_bn1m[i] = (float)mean;
        d_bn1r[i] = (float)rsqrt(var + 1e-5);
    }
}

// ---------------- fc2: u = bn1(x) @ w2^T + b2.  grid (32 f-tiles, 8 r-tiles, L), 256 thr, CTA 64x64.
__global__ void k_fc2(const float* __restrict__ w2, const float* __restrict__ b2,
                      const float* __restrict__ g1, const float* __restrict__ b1){
    const int i = blockIdx.z, r0 = blockIdx.y*64, f0 = blockIdx.x*64;
    const int tid = threadIdx.x, tx = tid&15, ty = tid>>4;
    const float alpha = g1[i]*d_bn1r[i];
    const float beta  = b1[i] - d_bn1m[i]*alpha;
    __shared__ float Xs[64][33], Ws[64][33];
    float acc[4][4];
#pragma unroll
    for (int u=0;u<4;u++)
#pragma unroll
        for (int v=0;v<4;v++) acc[u][v]=0.f;
    const float* xbase = d_x + (size_t)(i*512 + r0)*NS;
    const float* wbase = w2  + (size_t)(i*NF + f0)*NS;
    for (int kc=0; kc<NS; kc+=32){
        for (int idx=tid; idx<64*32; idx+=256){
            int rr = idx>>5, kk = idx&31;
            Xs[rr][kk] = xbase[(size_t)rr*NS + kc+kk]*alpha + beta;
        }
        for (int idx=tid; idx<64*32; idx+=256){
            int ff = idx>>5, kk = idx&31;
            Ws[ff][kk] = wbase[(size_t)ff*NS + kc+kk];
        }
        __syncthreads();
#pragma unroll
        for (int kk=0; kk<32; kk++){
            float a[4], bb[4];
#pragma unroll
            for (int u=0;u<4;u++) a[u]  = Xs[ty*4+u][kk];
#pragma unroll
            for (int v=0;v<4;v++) bb[v] = Ws[tx*4+v][kk];
#pragma unroll
            for (int u=0;u<4;u++)
#pragma unroll
                for (int v=0;v<4;v++) acc[u][v] = fmaf(a[u], bb[v], acc[u][v]);
        }
        __syncthreads();
    }
#pragma unroll
    for (int u=0;u<4;u++){
        int r = r0 + ty*4 + u;
#pragma unroll
        for (int v=0;v<4;v++){
            int f = f0 + tx*4 + v;
            d_u[(size_t)(i*512 + r)*NF + f] = acc[u][v] + b2[i*NF + f];
        }
    }
}

// ---------------- bn2 stats (per-feature mean/var over 512 rows)
__global__ void k_bn2(){
    const int i = blockIdx.y, f0 = blockIdx.x*64;
    const int tid = threadIdx.x, fx = tid&63, rg = tid>>6;
    const float* p = d_u + (size_t)i*512*NF + f0 + fx;
    float s=0.f, sq=0.f;
    for (int r=rg; r<512; r+=4){ float v = p[(size_t)r*NF]; s+=v; sq+=v*v; }
    __shared__ float ss[256], sqs[256];
    ss[tid]=s; sqs[tid]=sq; __syncthreads();
    if (rg==0){
        float S  = ss[fx]  + ss[fx+64]  + ss[fx+128]  + ss[fx+192];
        float SQ = sqs[fx] + sqs[fx+64] + sqs[fx+128] + sqs[fx+192];
        float mean = S/512.f;
        float var  = SQ/512.f - mean*mean;
        d_bn2m[i*NF+f0+fx] = mean;
        d_bn2r[i*NF+f0+fx] = rsqrtf(var + EPSF);
    }
}

// ---------------- fc3: y[row] = relu(bn2(u[row])) . w3   (one warp per row)
__global__ void k_fc3(const float* __restrict__ g2, const float* __restrict__ bb2,
                      const float* __restrict__ w3){
    const int row  = blockIdx.x*8 + (threadIdx.x>>5);   // 512 blocks x 8 warps = 4096 rows
    const int lane = threadIdx.x & 31;
    const int i = row >> 9;
    const float* up = d_u + (size_t)row*NF;
    float s = 0.f;
    for (int f=lane; f<NF; f+=32){
        int gi = i*NF + f;
        float z = g2[gi]*(up[f]-d_bn2m[gi])*d_bn2r[gi] + bb2[gi];
        z = fmaxf(z, 0.f);
        s = fmaf(z, w3[gi], s);
    }
#pragma unroll
    for (int off=16; off; off>>=1) s += __shfl_xor_sync(0xffffffffu, s, off);
    if (lane==0) d_y[row] = s;
}

// ---------------- final: pair-sum, bn3 per layer, accumulate, labels
__global__ void k_final(const float* __restrict__ b3, const float* __restrict__ g3,
                        const float* __restrict__ bb3, const int* __restrict__ targets,
                        float* __restrict__ out, int out_size){
    const int qk = threadIdx.x;   // 256
    __shared__ double ss[256], sqs[256];
    float accum = 0.f;
    for (int i=0;i<NL;i++){
        float p = d_y[i*512 + 2*qk] + d_y[i*512 + 2*qk + 1] + 2.f*b3[i];
        ss[qk] = (double)p; sqs[qk] = (double)p*(double)p;
        __syncthreads();
        for (int off=128; off; off>>=1){
            if (qk<off){ ss[qk]+=ss[qk+off]; sqs[qk]+=sqs[qk+off]; }
            __syncthreads();
        }
        double mean = ss[0]/256.0;
        double var  = sqs[0]/256.0 - mean*mean;
        float rstd  = (float)rsqrt(var + 1e-5);
        accum += g3[i]*((p - (float)mean)*rstd) + bb3[i];
        __syncthreads();   // protect ss/sqs before next layer overwrites
    }
    out[qk] = accum;
    if (out_size >= 512){
        int qq = qk >> 4, kk = qk & 15;
        out[256 + qk] = (targets[qq]==targets[kk]) ? 1.f : 0.f;
    }
}

// ---------------- launcher ----------------
extern "C" void kernel_launch(void* const* d_in, const int* in_sizes, int n_in,
                              void* d_out, int out_size){
    const float* q_feat = (const float*)d_in[0];
    const float* g_feat = (const float*)d_in[1];
    const int*   targets= (const int*)  d_in[2];
    const float* se     = (const float*)d_in[3];
    const float* fc0w   = (const float*)d_in[4];
    const float* fc0b   = (const float*)d_in[5];
    const float* bn1g   = (const float*)d_in[6];
    const float* bn1b   = (const float*)d_in[7];
    const float* fc2w   = (const float*)d_in[8];
    const float* fc2b   = (const float*)d_in[9];
    const float* bn2g   = (const float*)d_in[10];
    const float* bn2b   = (const float*)d_in[11];
    const float* fc3w   = (const float*)d_in[12];
    const float* fc3b   = (const float*)d_in[13];
    const float* bn3g   = (const float*)d_in[14];
    const float* bn3b   = (const float*)d_in[15];
    float* out = (float*)d_out;

    uint2 *p_qfs, *p_gfs, *p_w0s, *p_q2, *p_k2;
    cudaGetSymbolAddress((void**)&p_qfs, d_qfs);
    cudaGetSymbolAddress((void**)&p_gfs, d_gfs);
    cudaGetSymbolAddress((void**)&p_w0s, d_w0s);
    cudaGetSymbolAddress((void**)&p_q2,  d_query2);
    cudaGetSymbolAddress((void**)&p_k2,  d_key2);

    const int nfeat = NB*NL*ND*NS;
    const int nw0   = NL*ND*ND;

    k_sigse<<<(NL*NS*NS+255)/256, 256>>>(se);
    k_split<<<(nfeat+255)/256, 256>>>(q_feat, p_qfs, nfeat);
    k_split<<<(nfeat+255)/256, 256>>>(g_feat, p_gfs, nfeat);
    k_split<<<(nw0+255)/256,   256>>>(fc0w,   p_w0s, nw0);
    k_proj<<<dim3(16, NB, NL), 128>>>(p_qfs, fc0b, p_q2);
    k_proj<<<dim3(16, NB, NL), 128>>>(p_gfs, fc0b, p_k2);
    k_score<<<dim3(6, 256, NL), 128>>>();
    k_colmerge<<<(NL*256*NS+255)/256, 256>>>();
    k_bn1<<<NL, 512>>>();
    k_fc2<<<dim3(32, 8, NL), 256>>>(fc2w, fc2b, bn1g, bn1b);
    k_bn2<<<dim3(32, NL), 256>>>();
    k_fc3<<<512, 256>>>(bn2g, bn2b, fc3w);
    k_final<<<1, 256>>>(fc3b, bn3g, bn3b, targets, out, out_size);
}

// round 10
// speedup vs baseline: 1.7113x; 1.7113x over previous
#include <cuda_runtime.h>
#include <cuda_bf16.h>
#include <math.h>
#include <stdint.h>

#define NL 8
#define NS 192
#define ND 512
#define NF 2048
#define NB 16
#define EPSF 1e-5f

// ---------------- scratch (static device globals; no allocations) ----------------
__device__ uint32_t d_qfp  [NB*NL*ND*NS];      // packed bf16(hi,lo) q_feat  [b][i*D+d][t]
__device__ uint32_t d_gfp  [NB*NL*ND*NS];      // packed g_feat
__device__ uint32_t d_w0p  [NL*ND*ND];         // packed fc0_w   [i][e][d]
__device__ uint32_t d_qryp [NL*NB*NS*ND];      // packed query   [i][b][t][e]
__device__ uint32_t d_keyp [NL*NB*NS*ND];      // packed key     [i][b][s][e]
__device__ float d_sigse[NL*NS*NS];            // sigmoid(score_embed)
__device__ float d_x    [NL*512*NS];           // [i][r=2qk+branch][S]
__device__ float d_colp [NL*256*6*NS];         // per-t-tile colmax partials
__device__ float d_bn1m[NL], d_bn1r[NL];
__device__ float d_u    [NL*512*NF];           // fc2 output
__device__ float d_bn2m[NL*NF], d_bn2r[NL*NF];
__device__ float d_y    [NL*512];              // fc3 per-row output

// ---------------- bf16 split-pack helpers ----------------
// pack x ~= hi + lo (both bf16): low16 = hi, high16 = lo.
// 2-pass mma computes hiA*hiB + loA*hiB + hiA*loB (drops only loA*loB ~2^-18):
//   pass1: A=(hi,lo) x B=(hi,hi)  -> hiA*hiB + loA*hiB
//   pass2: A=(hi,hi) x B=(lo,0)   -> hiA*loB
__device__ __forceinline__ uint32_t packsplit(float x){
    __nv_bfloat16 h = __float2bfloat16(x);
    float r = x - __bfloat162float(h);
    __nv_bfloat16 l = __float2bfloat16(r);
    return (uint32_t)__bfloat16_as_ushort(h) | ((uint32_t)__bfloat16_as_ushort(l) << 16);
}
__device__ __forceinline__ uint32_t duphi(uint32_t p){ return __byte_perm(p, p, 0x1010); } // (hi,hi)
__device__ __forceinline__ uint32_t lozero(uint32_t p){ return __byte_perm(p, 0, 0x4432); } // (lo,0)

__device__ __forceinline__ void mma_bf16(float* c, const uint32_t* a, const uint32_t* b){
    asm volatile("mma.sync.aligned.m16n8k16.row.col.f32.bf16.bf16.f32 "
        "{%0,%1,%2,%3}, {%4,%5,%6,%7}, {%8,%9}, {%0,%1,%2,%3};"
        : "+f"(c[0]),"+f"(c[1]),"+f"(c[2]),"+f"(c[3])
        : "r"(a[0]),"r"(a[1]),"r"(a[2]),"r"(a[3]), "r"(b[0]),"r"(b[1]));
}

// ---------------- elementwise split-pack ----------------
__global__ void k_split(const float* __restrict__ src, uint32_t* __restrict__ dst, int n){
    int idx = blockIdx.x*256 + threadIdx.x;
    if (idx < n) dst[idx] = packsplit(src[idx]);
}

// ---------------- precompute sigmoid(score_embed) ----------------
__global__ void k_sigse(const float* __restrict__ se){
    int idx = blockIdx.x*256 + threadIdx.x;
    if (idx < NL*NS*NS) d_sigse[idx] = 1.f/(1.f+expf(-se[idx]));
}

// ---------------- fc0 projection (2-pass bf16-split mma, packed in/out)
// out[i][b][t][e] = sum_d feat[b][i*D+d][t] * w0[i][e][d] + b0[i][e]
// grid (16 e-tiles, B, L), 128 threads (4 warps). CTA: 192 t x 32 e, 16 elems/chunk.
#define PAS 200   // As stride: fragment loads conflict-free
__global__ void __launch_bounds__(128) k_proj(const uint32_t* __restrict__ featP,
                       const float* __restrict__ b0, uint32_t* __restrict__ outP){
    const int i = blockIdx.z, b = blockIdx.y, e0 = blockIdx.x*32;
    const int tid = threadIdx.x;
    const int w = tid>>5, lane = tid&31;
    const int g = lane>>2, c = lane&3;
    __shared__ uint32_t As[16*PAS];   // [kk][t]
    __shared__ uint32_t Bs[32*20];    // [e][kk]
    float acc[3][4][4];
#pragma unroll
    for (int mt=0;mt<3;mt++)
#pragma unroll
        for (int nt=0;nt<4;nt++)
#pragma unroll
            for (int r=0;r<4;r++) acc[mt][nt][r]=0.f;
    const uint32_t* fbase = featP + (size_t)(b*(ND*NL) + i*ND)*NS;
    const uint32_t* wbase = d_w0p + (size_t)i*ND*ND + (size_t)e0*ND;
    const int tb = w*48;
    for (int kc = 0; kc < ND; kc += 16){
        for (int idx = tid; idx < 16*NS; idx += 128){
            int kk = idx / NS, t = idx - kk*NS;
            As[kk*PAS + t] = fbase[(size_t)(kc+kk)*NS + t];
        }
        for (int idx = tid; idx < 32*16; idx += 128){
            int ee = idx >> 4, kk = idx & 15;
            Bs[ee*20 + kk] = wbase[(size_t)ee*ND + kc + kk];
        }
        __syncthreads();
#pragma unroll
        for (int ks=0; ks<2; ks++){
            const int k0 = ks*8;
            uint32_t bdup[4][2], blo0[4][2];
#pragma unroll
            for (int nt=0;nt<4;nt++){
                int e = nt*8 + g;
                uint32_t b0r = Bs[e*20 + k0 + c];
                uint32_t b1r = Bs[e*20 + k0 + 4 + c];
                bdup[nt][0] = duphi(b0r);  bdup[nt][1] = duphi(b1r);
                blo0[nt][0] = lozero(b0r); blo0[nt][1] = lozero(b1r);
            }
#pragma unroll
            for (int mt=0;mt<3;mt++){
                int r = tb + mt*16 + g;
                uint32_t araw[4], adup[4];
                araw[0] = As[(k0+c)*PAS + r];
                araw[1] = As[(k0+c)*PAS + r + 8];
                araw[2] = As[(k0+4+c)*PAS + r];
                araw[3] = As[(k0+4+c)*PAS + r + 8];
#pragma unroll
                for (int j=0;j<4;j++) adup[j] = duphi(araw[j]);
#pragma unroll
                for (int nt=0;nt<4;nt++){
                    mma_bf16(acc[mt][nt], araw, bdup[nt]);
                    mma_bf16(acc[mt][nt], adup, blo0[nt]);
                }
            }
        }
        __syncthreads();
    }
    // epilogue: + bias, split-pack, store 2 packed elems as uint2
    uint32_t* obase = outP + (size_t)(i*NB+b)*NS*ND;
#pragma unroll
    for (int nt=0;nt<4;nt++){
        int e = e0 + nt*8 + 2*c;
        float b01 = b0[i*ND + e], b11 = b0[i*ND + e + 1];
#pragma unroll
        for (int mt=0;mt<3;mt++){
            int r = tb + mt*16 + g;
            uint2 v0 = make_uint2(packsplit(acc[mt][nt][0] + b01), packsplit(acc[mt][nt][1] + b11));
            uint2 v1 = make_uint2(packsplit(acc[mt][nt][2] + b01), packsplit(acc[mt][nt][3] + b11));
            *reinterpret_cast<uint2*>(&obase[(size_t)r*ND + e])     = v0;
            *reinterpret_cast<uint2*>(&obase[(size_t)(r+8)*ND + e]) = v1;
        }
    }
}

// ---------------- score GEMM (2-pass bf16-split mma) + mask + max pooling
// grid (6 t-tiles, 256 qk, L), 128 threads (4 warps). CTA: s=192 x t=32, 16 elems/chunk.
__global__ void __launch_bounds__(128) k_score(){
    const int i = blockIdx.z, qk = blockIdx.y, tt = blockIdx.x;
    const int q = qk >> 4, k = qk & 15;
    const int t0 = tt*32;
    const int tid = threadIdx.x;
    const int w = tid>>5, lane = tid&31;
    const int g = lane>>2, c = lane&3;
    __shared__ uint32_t As[NS*20];    // key  [s][kk]
    __shared__ uint32_t Bs[32*20];    // query[t][kk]
    __shared__ float rowsm[4][32];
    float acc[3][4][4];
#pragma unroll
    for (int mt=0;mt<3;mt++)
#pragma unroll
        for (int nt=0;nt<4;nt++)
#pragma unroll
            for (int r=0;r<4;r++) acc[mt][nt][r]=0.f;
    const uint32_t* kbase = d_keyp + (size_t)(i*NB+k)*NS*ND;
    const uint32_t* qbase = d_qryp + (size_t)(i*NB+q)*NS*ND + (size_t)t0*ND;
    const int sb = w*48;
    for (int kc=0; kc<ND; kc+=16){
        for (int idx=tid; idx<NS*16; idx+=128){
            int s = idx>>4, kk = idx&15;
            As[s*20 + kk] = kbase[(size_t)s*ND + kc+kk];
        }
        for (int idx=tid; idx<32*16; idx+=128){
            int tv = idx>>4, kk = idx&15;
            Bs[tv*20 + kk] = qbase[(size_t)tv*ND + kc+kk];
        }
        __syncthreads();
#pragma unroll
        for (int ks=0; ks<2; ks++){
            const int k0 = ks*8;
            uint32_t bdup[4][2], blo0[4][2];
#pragma unroll
            for (int nt=0;nt<4;nt++){
                int t = nt*8 + g;
                uint32_t b0r = Bs[t*20 + k0 + c];
                uint32_t b1r = Bs[t*20 + k0 + 4 + c];
                bdup[nt][0] = duphi(b0r);  bdup[nt][1] = duphi(b1r);
                blo0[nt][0] = lozero(b0r); blo0[nt][1] = lozero(b1r);
            }
#pragma unroll
            for (int mt=0;mt<3;mt++){
                int s = sb + mt*16 + g;
                uint32_t araw[4], adup[4];
                araw[0] = As[s*20 + k0 + c];
                araw[1] = As[(s+8)*20 + k0 + c];
                araw[2] = As[s*20 + k0 + 4 + c];
                araw[3] = As[(s+8)*20 + k0 + 4 + c];
#pragma unroll
                for (int j=0;j<4;j++) adup[j] = duphi(araw[j]);
#pragma unroll
                for (int nt=0;nt<4;nt++){
                    mma_bf16(acc[mt][nt], araw, bdup[nt]);
                    mma_bf16(acc[mt][nt], adup, blo0[nt]);
                }
            }
        }
        __syncthreads();
    }
    // mask by sigmoid(score_embed): acc[mt][nt][{0,1,2,3}] ~ (s0,t0),(s0,t0+1),(s0+8,t0),(s0+8,t0+1)
    const float* sbase = d_sigse + (size_t)i*NS*NS;
#pragma unroll
    for (int mt=0;mt<3;mt++){
        int r0 = sb + mt*16 + g, r1 = r0 + 8;
#pragma unroll
        for (int nt=0;nt<4;nt++){
            int tc = t0 + nt*8 + 2*c;
            acc[mt][nt][0] *= sbase[r0*NS + tc];
            acc[mt][nt][1] *= sbase[r0*NS + tc + 1];
            acc[mt][nt][2] *= sbase[r1*NS + tc];
            acc[mt][nt][3] *= sbase[r1*NS + tc + 1];
        }
    }
    // ---- rowmax: max over s (per t column) ----
    float rm[4][2];
#pragma unroll
    for (int nt=0;nt<4;nt++){
        float m0 = fmaxf(acc[0][nt][0], acc[0][nt][2]);
        float m1 = fmaxf(acc[0][nt][1], acc[0][nt][3]);
#pragma unroll
        for (int mt=1;mt<3;mt++){
            m0 = fmaxf(m0, fmaxf(acc[mt][nt][0], acc[mt][nt][2]));
            m1 = fmaxf(m1, fmaxf(acc[mt][nt][1], acc[mt][nt][3]));
        }
        rm[nt][0] = m0; rm[nt][1] = m1;
    }
#pragma unroll
    for (int off=4; off<32; off<<=1)
#pragma unroll
        for (int nt=0;nt<4;nt++){
            rm[nt][0] = fmaxf(rm[nt][0], __shfl_xor_sync(0xffffffffu, rm[nt][0], off));
            rm[nt][1] = fmaxf(rm[nt][1], __shfl_xor_sync(0xffffffffu, rm[nt][1], off));
        }
    if (lane < 4){
#pragma unroll
        for (int nt=0;nt<4;nt++){
            rowsm[w][nt*8 + 2*lane]     = rm[nt][0];
            rowsm[w][nt*8 + 2*lane + 1] = rm[nt][1];
        }
    }
    __syncthreads();
    if (tid < 32){
        float m = fmaxf(fmaxf(rowsm[0][tid], rowsm[1][tid]), fmaxf(rowsm[2][tid], rowsm[3][tid]));
        d_x[((size_t)i*512 + 2*qk)*NS + t0 + tid] = m;
    }
    // ---- colmax: max over this tile's 32 t (per s row); partial across t-tiles ----
    float cm[3][2];
#pragma unroll
    for (int mt=0;mt<3;mt++){
        float m0 = fmaxf(acc[mt][0][0], acc[mt][0][1]);
        float m1 = fmaxf(acc[mt][0][2], acc[mt][0][3]);
#pragma unroll
        for (int nt=1;nt<4;nt++){
            m0 = fmaxf(m0, fmaxf(acc[mt][nt][0], acc[mt][nt][1]));
            m1 = fmaxf(m1, fmaxf(acc[mt][nt][2], acc[mt][nt][3]));
        }
        cm[mt][0] = m0; cm[mt][1] = m1;
    }
#pragma unroll
    for (int off=1; off<4; off<<=1)
#pragma unroll
        for (int mt=0;mt<3;mt++){
            cm[mt][0] = fmaxf(cm[mt][0], __shfl_xor_sync(0xffffffffu, cm[mt][0], off));
            cm[mt][1] = fmaxf(cm[mt][1], __shfl_xor_sync(0xffffffffu, cm[mt][1], off));
        }
    if (c == 0){
        float* cpb = d_colp + ((size_t)(i*256+qk)*6 + tt)*NS;
#pragma unroll
        for (int mt=0;mt<3;mt++){
            int r = sb + mt*16 + g;
            cpb[r]     = cm[mt][0];
            cpb[r + 8] = cm[mt][1];
        }
    }
}

// ---------------- merge colmax partials (6 t-tiles) into odd rows of x
__global__ void k_colmerge(){
    int idx = blockIdx.x*256 + threadIdx.x;       // NL*256*NS = 393216
    if (idx >= NL*256*NS) return;
    int s   = idx % NS;
    int iqk = idx / NS;
    int i   = iqk >> 8;
    int qk  = iqk & 255;
    const float* p = d_colp + (size_t)iqk*6*NS + s;
    float m = p[0];
#pragma unroll
    for (int j=1;j<6;j++) m = fmaxf(m, p[(size_t)j*NS]);
    d_x[((size_t)i*512 + 2*qk + 1)*NS + s] = m;
}

// ---------------- bn1 stats (whole-tensor mean/var per layer), double accum
__global__ void k_bn1(){
    const int i = blockIdx.x, tid = threadIdx.x;   // 8 blocks x 512 threads
    const float* p = d_x + (size_t)i*512*NS;
    double s=0.0, sq=0.0;
    for (int idx=tid; idx<512*NS; idx+=512){ double v = p[idx]; s+=v; sq+=v*v; }
    __shared__ double ss[512], sqs[512];
    ss[tid]=s; sqs[tid]=sq; __syncthreads();
    for (int off=256; off; off>>=1){
        if (tid<off){ ss[tid]+=ss[tid+off]; sqs[tid]+=sqs[tid+off]; }
        __syncthreads();
    }
    if (tid==0){
        double n = 512.0*NS;
        double mean = ss[0]/n;
        double var  = sqs[0]/n - mean*mean;
        d_bn1m[i] = (float)mean;
        d_bn1r[i] = (float)rsqrt(var + 1e-5);
    }
}

// ---------------- fc2: u = bn1(x) @ w2^T + b2.  grid (32 f-tiles, 8 r-tiles, L), 256 thr, CTA 64x64.
__global__ void k_fc2(const float* __restrict__ w2, const float* __restrict__ b2,
                      const float* __restrict__ g1, const float* __restrict__ b1){
    const int i = blockIdx.z, r0 = blockIdx.y*64, f0 = blockIdx.x*64;
    const int tid = threadIdx.x, tx = tid&15, ty = tid>>4;
    const float alpha = g1[i]*d_bn1r[i];
    const float beta  = b1[i] - d_bn1m[i]*alpha;
    __shared__ float Xs[64][33], Ws[64][33];
    float acc[4][4];
#pragma unroll
    for (int u=0;u<4;u++)
#pragma unroll
        for (int v=0;v<4;v++) acc[u][v]=0.f;
    const float* xbase = d_x + (size_t)(i*512 + r0)*NS;
    const float* wbase = w2  + (size_t)(i*NF + f0)*NS;
    for (int kc=0; kc<NS; kc+=32){
        for (int idx=tid; idx<64*32; idx+=256){
            int rr = idx>>5, kk = idx&31;
            Xs[rr][kk] = xbase[(size_t)rr*NS + kc+kk]*alpha + beta;
        }
        for (int idx=tid; idx<64*32; idx+=256){
            int ff = idx>>5, kk = idx&31;
            Ws[ff][kk] = wbase[(size_t)ff*NS + kc+kk];
        }
        __syncthreads();
#pragma unroll
        for (int kk=0; kk<32; kk++){
            float a[4], bb[4];
#pragma unroll
            for (int u=0;u<4;u++) a[u]  = Xs[ty*4+u][kk];
#pragma unroll
            for (int v=0;v<4;v++) bb[v] = Ws[tx*4+v][kk];
#pragma unroll
            for (int u=0;u<4;u++)
#pragma unroll
                for (int v=0;v<4;v++) acc[u][v] = fmaf(a[u], bb[v], acc[u][v]);
        }
        __syncthreads();
    }
#pragma unroll
    for (int u=0;u<4;u++){
        int r = r0 + ty*4 + u;
#pragma unroll
        for (int v=0;v<4;v++){
            int f = f0 + tx*4 + v;
            d_u[(size_t)(i*512 + r)*NF + f] = acc[u][v] + b2[i*NF + f];
        }
    }
}

// ---------------- bn2 stats (per-feature mean/var over 512 rows)
__global__ void k_bn2(){
    const int i = blockIdx.y, f0 = blockIdx.x*64;
    const int tid = threadIdx.x, fx = tid&63, rg = tid>>6;
    const float* p = d_u + (size_t)i*512*NF + f0 + fx;
    float s=0.f, sq=0.f;
    for (int r=rg; r<512; r+=4){ float v = p[(size_t)r*NF]; s+=v; sq+=v*v; }
    __shared__ float ss[256], sqs[256];
    ss[tid]=s; sqs[tid]=sq; __syncthreads();
    if (rg==0){
        float S  = ss[fx]  + ss[fx+64]  + ss[fx+128]  + ss[fx+192];
        float SQ = sqs[fx] + sqs[fx+64] + sqs[fx+128] + sqs[fx+192];
        float mean = S/512.f;
        float var  = SQ/512.f - mean*mean;
        d_bn2m[i*NF+f0+fx] = mean;
        d_bn2r[i*NF+f0+fx] = rsqrtf(var + EPSF);
    }
}

// ---------------- fc3: y[row] = relu(bn2(u[row])) . w3   (one warp per row)
__global__ void k_fc3(const float* __restrict__ g2, const float* __restrict__ bb2,
                      const float* __restrict__ w3){
    const int row  = blockIdx.x*8 + (threadIdx.x>>5);   // 512 blocks x 8 warps = 4096 rows
    const int lane = threadIdx.x & 31;
    const int i = row >> 9;
    const float* up = d_u + (size_t)row*NF;
    float s = 0.f;
    for (int f=lane; f<NF; f+=32){
        int gi = i*NF + f;
        float z = g2[gi]*(up[f]-d_bn2m[gi])*d_bn2r[gi] + bb2[gi];
        z = fmaxf(z, 0.f);
        s = fmaf(z, w3[gi], s);
    }
#pragma unroll
    for (int off=16; off; off>>=1) s += __shfl_xor_sync(0xffffffffu, s, off);
    if (lane==0) d_y[row] = s;
}

// ---------------- final: pair-sum, bn3 per layer, accumulate, labels
__global__ void k_final(const float* __restrict__ b3, const float* __restrict__ g3,
                        const float* __restrict__ bb3, const int* __restrict__ targets,
                        float* __restrict__ out, int out_size){
    const int qk = threadIdx.x;   // 256
    __shared__ double ss[256], sqs[256];
    float accum = 0.f;
    for (int i=0;i<NL;i++){
        float p = d_y[i*512 + 2*qk] + d_y[i*512 + 2*qk + 1] + 2.f*b3[i];
        ss[qk] = (double)p; sqs[qk] = (double)p*(double)p;
        __syncthreads();
        for (int off=128; off; off>>=1){
            if (qk<off){ ss[qk]+=ss[qk+off]; sqs[qk]+=sqs[qk+off]; }
            __syncthreads();
        }
        double mean = ss[0]/256.0;
        double var  = sqs[0]/256.0 - mean*mean;
        float rstd  = (float)rsqrt(var + 1e-5);
        accum += g3[i]*((p - (float)mean)*rstd) + bb3[i];
        __syncthreads();   // protect ss/sqs before next layer overwrites
    }
    out[qk] = accum;
    if (out_size >= 512){
        int qq = qk >> 4, kk = qk & 15;
        out[256 + qk] = (targets[qq]==targets[kk]) ? 1.f : 0.f;
    }
}

// ---------------- launcher ----------------
extern "C" void kernel_launch(void* const* d_in, const int* in_sizes, int n_in,
                              void* d_out, int out_size){
    const float* q_feat = (const float*)d_in[0];
    const float* g_feat = (const float*)d_in[1];
    const int*   targets= (const int*)  d_in[2];
    const float* se     = (const float*)d_in[3];
    const float* fc0w   = (const float*)d_in[4];
    const float* fc0b   = (const float*)d_in[5];
    const float* bn1g   = (const float*)d_in[6];
    const float* bn1b   = (const float*)d_in[7];
    const float* fc2w   = (const float*)d_in[8];
    const float* fc2b   = (const float*)d_in[9];
    const float* bn2g   = (const float*)d_in[10];
    const float* bn2b   = (const float*)d_in[11];
    const float* fc3w   = (const float*)d_in[12];
    const float* fc3b   = (const float*)d_in[13];
    const float* bn3g   = (const float*)d_in[14];
    const float* bn3b   = (const float*)d_in[15];
    float* out = (float*)d_out;

    uint32_t *p_qfp, *p_gfp, *p_w0p, *p_qryp, *p_keyp;
    cudaGetSymbolAddress((void**)&p_qfp,  d_qfp);
    cudaGetSymbolAddress((void**)&p_gfp,  d_gfp);
    cudaGetSymbolAddress((void**)&p_w0p,  d_w0p);
    cudaGetSymbolAddress((void**)&p_qryp, d_qryp);
    cudaGetSymbolAddress((void**)&p_keyp, d_keyp);

    const int nfeat = NB*NL*ND*NS;
    const int nw0   = NL*ND*ND;

    k_sigse<<<(NL*NS*NS+255)/256, 256>>>(se);
    k_split<<<(nfeat+255)/256, 256>>>(q_feat, p_qfp, nfeat);
    k_split<<<(nfeat+255)/256, 256>>>(g_feat, p_gfp, nfeat);
    k_split<<<(nw0+255)/256,   256>>>(fc0w,   p_w0p, nw0);
    k_proj<<<dim3(16, NB, NL), 128>>>(p_qfp, fc0b, p_qryp);
    k_proj<<<dim3(16, NB, NL), 128>>>(p_gfp, fc0b, p_keyp);
    k_score<<<dim3(6, 256, NL), 128>>>();
    k_colmerge<<<(NL*256*NS+255)/256, 256>>>();
    k_bn1<<<NL, 512>>>();
    k_fc2<<<dim3(32, 8, NL), 256>>>(fc2w, fc2b, bn1g, bn1b);
    k_bn2<<<dim3(32, NL), 256>>>();
    k_fc3<<<512, 256>>>(bn2g, bn2b, fc3w);
    k_final<<<1, 256>>>(fc3b, bn3g, bn3b, targets, out, out_size);
}

// round 12
// speedup vs baseline: 1.9320x; 1.1289x over previous
#include <cuda_runtime.h>
#include <cuda_bf16.h>
#include <math.h>
#include <stdint.h>

#define NL 8
#define NS 192
#define ND 512
#define NF 2048
#define NB 16
#define EPSF 1e-5f

// ---------------- scratch (static device globals; no allocations) ----------------
__device__ uint32_t d_qfp  [NB*NL*ND*NS];      // packed bf16(hi,lo) q_feat  [b][i*D+d][t]
__device__ uint32_t d_gfp  [NB*NL*ND*NS];      // packed g_feat
__device__ uint32_t d_w0p  [NL*ND*ND];         // packed fc0_w   [i][e][d]
__device__ uint32_t d_qryp [NL*NB*NS*ND];      // packed query   [i][b][t][e]
__device__ uint32_t d_keyp [NL*NB*NS*ND];      // packed key     [i][b][s][e]
__device__ float d_sigse[NL*NS*NS];            // sigmoid(score_embed)
__device__ float d_x    [NL*512*NS];           // [i][r=2qk+branch][S]
__device__ float d_rowp [NL*256*2*NS];         // rowmax partials (2 s-halves)
__device__ float d_bn1m[NL], d_bn1r[NL];
__device__ float d_u    [NL*512*NF];           // fc2 output
__device__ float d_bn2m[NL*NF], d_bn2r[NL*NF];
__device__ float d_y    [NL*512];              // fc3 per-row output

// ---------------- bf16 split-pack helpers ----------------
// pack x ~= hi + lo (both bf16): low16 = hi, high16 = lo.
// 2-pass mma: pass1 A=(hi,lo) x B=(hi,hi) -> hiA*hiB + loA*hiB
//             pass2 A=(hi,hi) x B=(lo,0)  -> hiA*loB   (drops only loA*loB ~2^-18)
__device__ __forceinline__ uint32_t packsplit(float x){
    __nv_bfloat16 h = __float2bfloat16(x);
    float r = x - __bfloat162float(h);
    __nv_bfloat16 l = __float2bfloat16(r);
    return (uint32_t)__bfloat16_as_ushort(h) | ((uint32_t)__bfloat16_as_ushort(l) << 16);
}
__device__ __forceinline__ uint32_t duphi(uint32_t p){ return __byte_perm(p, p, 0x1010); } // (hi,hi)
__device__ __forceinline__ uint32_t lozero(uint32_t p){ return __byte_perm(p, 0, 0x4432); } // (lo,0)

__device__ __forceinline__ void mma_bf16(float* c, const uint32_t* a, const uint32_t* b){
    asm volatile("mma.sync.aligned.m16n8k16.row.col.f32.bf16.bf16.f32 "
        "{%0,%1,%2,%3}, {%4,%5,%6,%7}, {%8,%9}, {%0,%1,%2,%3};"
        : "+f"(c[0]),"+f"(c[1]),"+f"(c[2]),"+f"(c[3])
        : "r"(a[0]),"r"(a[1]),"r"(a[2]),"r"(a[3]), "r"(b[0]),"r"(b[1]));
}

// ---------------- elementwise split-pack ----------------
__global__ void k_split(const float* __restrict__ src, uint32_t* __restrict__ dst, int n){
    int idx = blockIdx.x*256 + threadIdx.x;
    if (idx < n) dst[idx] = packsplit(src[idx]);
}

// ---------------- precompute sigmoid(score_embed) ----------------
__global__ void k_sigse(const float* __restrict__ se){
    int idx = blockIdx.x*256 + threadIdx.x;
    if (idx < NL*NS*NS) d_sigse[idx] = 1.f/(1.f+expf(-se[idx]));
}

// ---------------- fc0 projection (2-pass bf16-split mma)
// out[i][b][t][e] = sum_d feat[b][i*D+d][t] * w0[i][e][d] + b0[i][e]
// grid (8 e-tiles, B, L), 256 threads (8 warps). CTA: 192 t x 64 e, 16 elems/chunk.
// warp w: mw=w>>1 -> t-base mw*48 (3 m-tiles), nw=w&1 -> e-base nw*32 (4 n-tiles).
#define PAS 200
__global__ void __launch_bounds__(256) k_proj(const uint32_t* __restrict__ featP,
                       const float* __restrict__ b0, uint32_t* __restrict__ outP){
    const int i = blockIdx.z, b = blockIdx.y, e0 = blockIdx.x*64;
    const int tid = threadIdx.x;
    const int w = tid>>5, lane = tid&31;
    const int g = lane>>2, c = lane&3;
    const int mw = w>>1, nw = w&1;
    __shared__ uint32_t As[16*PAS];   // [kk][t]
    __shared__ uint32_t Bs[64*20];    // [e][kk]
    float acc[3][4][4];
#pragma unroll
    for (int mt=0;mt<3;mt++)
#pragma unroll
        for (int nt=0;nt<4;nt++)
#pragma unroll
            for (int r=0;r<4;r++) acc[mt][nt][r]=0.f;
    const uint32_t* fbase = featP + (size_t)(b*(ND*NL) + i*ND)*NS;
    const uint32_t* wbase = d_w0p + (size_t)i*ND*ND + (size_t)e0*ND;
    const int tb = mw*48;
    for (int kc = 0; kc < ND; kc += 16){
        for (int idx = tid; idx < 16*NS; idx += 256){
            int kk = idx / NS, t = idx - kk*NS;
            As[kk*PAS + t] = fbase[(size_t)(kc+kk)*NS + t];
        }
        for (int idx = tid; idx < 64*16; idx += 256){
            int ee = idx >> 4, kk = idx & 15;
            Bs[ee*20 + kk] = wbase[(size_t)ee*ND + kc + kk];
        }
        __syncthreads();
#pragma unroll
        for (int ks=0; ks<2; ks++){
            const int k0 = ks*8;
            uint32_t bdup[4][2], blo0[4][2];
#pragma unroll
            for (int nt=0;nt<4;nt++){
                int e = nw*32 + nt*8 + g;
                uint32_t b0r = Bs[e*20 + k0 + c];
                uint32_t b1r = Bs[e*20 + k0 + 4 + c];
                bdup[nt][0] = duphi(b0r);  bdup[nt][1] = duphi(b1r);
                blo0[nt][0] = lozero(b0r); blo0[nt][1] = lozero(b1r);
            }
#pragma unroll
            for (int mt=0;mt<3;mt++){
                int r = tb + mt*16 + g;
                uint32_t araw[4], adup[4];
                araw[0] = As[(k0+c)*PAS + r];
                araw[1] = As[(k0+c)*PAS + r + 8];
                araw[2] = As[(k0+4+c)*PAS + r];
                araw[3] = As[(k0+4+c)*PAS + r + 8];
#pragma unroll
                for (int j=0;j<4;j++) adup[j] = duphi(araw[j]);
#pragma unroll
                for (int nt=0;nt<4;nt++){
                    mma_bf16(acc[mt][nt], araw, bdup[nt]);
                    mma_bf16(acc[mt][nt], adup, blo0[nt]);
                }
            }
        }
        __syncthreads();
    }
    // epilogue: + bias, split-pack, store 2 packed elems as uint2
    uint32_t* obase = outP + (size_t)(i*NB+b)*NS*ND;
#pragma unroll
    for (int nt=0;nt<4;nt++){
        int e = e0 + nw*32 + nt*8 + 2*c;
        float b01 = b0[i*ND + e], b11 = b0[i*ND + e + 1];
#pragma unroll
        for (int mt=0;mt<3;mt++){
            int r = tb + mt*16 + g;
            uint2 v0 = make_uint2(packsplit(acc[mt][nt][0] + b01), packsplit(acc[mt][nt][1] + b11));
            uint2 v1 = make_uint2(packsplit(acc[mt][nt][2] + b01), packsplit(acc[mt][nt][3] + b11));
            *reinterpret_cast<uint2*>(&obase[(size_t)r*ND + e])     = v0;
            *reinterpret_cast<uint2*>(&obase[(size_t)(r+8)*ND + e]) = v1;
        }
    }
}

// ---------------- score GEMM (2-pass bf16-split) + mask + max pooling
// grid (2 s-halves, 256 qk, L), 256 threads (8 warps). CTA: M = t 192 (full q) x N = s 96.
// warp w: mw=w>>1 -> t-base mw*48 (3 m-tiles), nw=w&1 -> s-base nw*48 (6 n-tiles).
// colmax (over t) direct write; rowmax (over s) -> 2 partials merged by k_rowmerge.
__global__ void __launch_bounds__(256) k_score(){
    const int i = blockIdx.z, qk = blockIdx.y, sh = blockIdx.x;
    const int q = qk >> 4, k = qk & 15;
    const int s0 = sh*96;
    const int tid = threadIdx.x;
    const int w = tid>>5, lane = tid&31;
    const int g = lane>>2, c = lane&3;
    const int mw = w>>1, nw = w&1;
    __shared__ uint32_t As[NS*20];    // query [t][kk]
    __shared__ uint32_t Bs[96*20];    // key   [s][kk]
    __shared__ float rowbuf[8][48];
    __shared__ float colbuf[8][48];
    float acc[3][6][4];
#pragma unroll
    for (int mt=0;mt<3;mt++)
#pragma unroll
        for (int nt=0;nt<6;nt++)
#pragma unroll
            for (int r=0;r<4;r++) acc[mt][nt][r]=0.f;
    const uint32_t* qbase = d_qryp + (size_t)(i*NB+q)*NS*ND;
    const uint32_t* kbase = d_keyp + (size_t)(i*NB+k)*NS*ND + (size_t)s0*ND;
    const int tb = mw*48, sb = nw*48;
    for (int kc=0; kc<ND; kc+=16){
        for (int idx=tid; idx<NS*16; idx+=256){
            int t = idx>>4, kk = idx&15;
            As[t*20 + kk] = qbase[(size_t)t*ND + kc+kk];
        }
        for (int idx=tid; idx<96*16; idx+=256){
            int s = idx>>4, kk = idx&15;
            Bs[s*20 + kk] = kbase[(size_t)s*ND + kc+kk];
        }
        __syncthreads();
#pragma unroll
        for (int ks=0; ks<2; ks++){
            const int k0 = ks*8;
            uint32_t bdup[6][2], blo0[6][2];
#pragma unroll
            for (int nt=0;nt<6;nt++){
                int s = sb + nt*8 + g;
                uint32_t b0r = Bs[s*20 + k0 + c];
                uint32_t b1r = Bs[s*20 + k0 + 4 + c];
                bdup[nt][0] = duphi(b0r);  bdup[nt][1] = duphi(b1r);
                blo0[nt][0] = lozero(b0r); blo0[nt][1] = lozero(b1r);
            }
#pragma unroll
            for (int mt=0;mt<3;mt++){
                int t = tb + mt*16 + g;
                uint32_t araw[4], adup[4];
                araw[0] = As[t*20 + k0 + c];
                araw[1] = As[(t+8)*20 + k0 + c];
                araw[2] = As[t*20 + k0 + 4 + c];
                araw[3] = As[(t+8)*20 + k0 + 4 + c];
#pragma unroll
                for (int j=0;j<4;j++) adup[j] = duphi(araw[j]);
#pragma unroll
                for (int nt=0;nt<6;nt++){
                    mma_bf16(acc[mt][nt], araw, bdup[nt]);
                    mma_bf16(acc[mt][nt], adup, blo0[nt]);
                }
            }
        }
        __syncthreads();
    }
    // mask by sigmoid(score_embed): element (row=t, col=s) *= sigse[s*NS + t]
    // acc[mt][nt][{0,1,2,3}] -> (t0,s0'),(t0,s0'+1),(t0+8,s0'),(t0+8,s0'+1)
    const float* sbase = d_sigse + (size_t)i*NS*NS;
#pragma unroll
    for (int mt=0;mt<3;mt++){
        int t0v = tb + mt*16 + g, t1v = t0v + 8;
#pragma unroll
        for (int nt=0;nt<6;nt++){
            int sc = s0 + sb + nt*8 + 2*c;
            acc[mt][nt][0] *= sbase[(size_t)sc*NS + t0v];
            acc[mt][nt][1] *= sbase[(size_t)(sc+1)*NS + t0v];
            acc[mt][nt][2] *= sbase[(size_t)sc*NS + t1v];
            acc[mt][nt][3] *= sbase[(size_t)(sc+1)*NS + t1v];
        }
    }
    // ---- rowmax partial: max over this CTA's 96 s, per t row ----
    float rm[3][2];
#pragma unroll
    for (int mt=0;mt<3;mt++){
        float m0 = fmaxf(acc[mt][0][0], acc[mt][0][1]);
        float m1 = fmaxf(acc[mt][0][2], acc[mt][0][3]);
#pragma unroll
        for (int nt=1;nt<6;nt++){
            m0 = fmaxf(m0, fmaxf(acc[mt][nt][0], acc[mt][nt][1]));
            m1 = fmaxf(m1, fmaxf(acc[mt][nt][2], acc[mt][nt][3]));
        }
        rm[mt][0] = m0; rm[mt][1] = m1;
    }
#pragma unroll
    for (int off=1; off<4; off<<=1)
#pragma unroll
        for (int mt=0;mt<3;mt++){
            rm[mt][0] = fmaxf(rm[mt][0], __shfl_xor_sync(0xffffffffu, rm[mt][0], off));
            rm[mt][1] = fmaxf(rm[mt][1], __shfl_xor_sync(0xffffffffu, rm[mt][1], off));
        }
    if (c == 0){
#pragma unroll
        for (int mt=0;mt<3;mt++){
            rowbuf[w][mt*16 + g]     = rm[mt][0];
            rowbuf[w][mt*16 + g + 8] = rm[mt][1];
        }
    }
    // ---- colmax: max over all 192 t (full in CTA), per s col ----
    float cm[6][2];
#pragma unroll
    for (int nt=0;nt<6;nt++){
        float m0 = fmaxf(acc[0][nt][0], acc[0][nt][2]);
        float m1 = fmaxf(acc[0][nt][1], acc[0][nt][3]);
#pragma unroll
        for (int mt=1;mt<3;mt++){
            m0 = fmaxf(m0, fmaxf(acc[mt][nt][0], acc[mt][nt][2]));
            m1 = fmaxf(m1, fmaxf(acc[mt][nt][1], acc[mt][nt][3]));
        }
        cm[nt][0] = m0; cm[nt][1] = m1;
    }
#pragma unroll
    for (int off=4; off<32; off<<=1)
#pragma unroll
        for (int nt=0;nt<6;nt++){
            cm[nt][0] = fmaxf(cm[nt][0], __shfl_xor_sync(0xffffffffu, cm[nt][0], off));
            cm[nt][1] = fmaxf(cm[nt][1], __shfl_xor_sync(0xffffffffu, cm[nt][1], off));
        }
    if (g == 0){
#pragma unroll
        for (int nt=0;nt<6;nt++){
            colbuf[w][nt*8 + 2*c]     = cm[nt][0];
            colbuf[w][nt*8 + 2*c + 1] = cm[nt][1];
        }
    }
    __syncthreads();
    // merge across warps: 192 rowmax entries + 96 colmax entries = 288 items, strided
    for (int idx = tid; idx < NS + 96; idx += 256){
        if (idx < NS){   // rowmax partial: merge 2 n-warps for this t row
            int mwv = idx / 48, j = idx % 48;
            float v = fmaxf(rowbuf[mwv*2][j], rowbuf[mwv*2+1][j]);
            d_rowp[(((size_t)i*256 + qk)*2 + sh)*NS + idx] = v;
        } else {         // colmax: merge 4 m-warps, direct write odd row
            int sl = idx - NS;
            int nwv = sl / 48, j = sl % 48;
            float v = colbuf[nwv][j];
#pragma unroll
            for (int mwv=1; mwv<4; mwv++) v = fmaxf(v, colbuf[mwv*2 + nwv][j]);
            d_x[((size_t)i*512 + 2*qk + 1)*NS + s0 + sl] = v;
        }
    }
}

// ---------------- merge rowmax partials (2 s-halves) into even rows of x
__global__ void k_rowmerge(){
    int idx = blockIdx.x*256 + threadIdx.x;       // NL*256*NS = 393216
    if (idx >= NL*256*NS) return;
    int t   = idx % NS;
    int iqk = idx / NS;
    int i   = iqk >> 8;
    int qk  = iqk & 255;
    const float* p = d_rowp + (size_t)iqk*2*NS + t;
    d_x[((size_t)i*512 + 2*qk)*NS + t] = fmaxf(p[0], p[NS]);
}

// ---------------- bn1 stats (whole-tensor mean/var per layer), double accum
__global__ void k_bn1(){
    const int i = blockIdx.x, tid = threadIdx.x;   // 8 blocks x 512 threads
    const float* p = d_x + (size_t)i*512*NS;
    double s=0.0, sq=0.0;
    for (int idx=tid; idx<512*NS; idx+=512){ double v = p[idx]; s+=v; sq+=v*v; }
    __shared__ double ss[512], sqs[512];
    ss[tid]=s; sqs[tid]=sq; __syncthreads();
    for (int off=256; off; off>>=1){
        if (tid<off){ ss[tid]+=ss[tid+off]; sqs[tid]+=sqs[tid+off]; }
        __syncthreads();
    }
    if (tid==0){
        double n = 512.0*NS;
        double mean = ss[0]/n;
        double var  = sqs[0]/n - mean*mean;
        d_bn1m[i] = (float)mean;
        d_bn1r[i] = (float)rsqrt(var + 1e-5);
    }
}

// ---------------- fc2: u = bn1(x) @ w2^T + b2.  grid (32 f-tiles, 8 r-tiles, L), 256 thr, CTA 64x64.
__global__ void k_fc2(const float* __restrict__ w2, const float* __restrict__ b2,
                      const float* __restrict__ g1, const float* __restrict__ b1){
    const int i = blockIdx.z, r0 = blockIdx.y*64, f0 = blockIdx.x*64;
    const int tid = threadIdx.x, tx = tid&15, ty = tid>>4;
    const float alpha = g1[i]*d_bn1r[i];
    const float beta  = b1[i] - d_bn1m[i]*alpha;
    __shared__ float Xs[64][33], Ws[64][33];
    float acc[4][4];
#pragma unroll
    for (int u=0;u<4;u++)
#pragma unroll
        for (int v=0;v<4;v++) acc[u][v]=0.f;
    const float* xbase = d_x + (size_t)(i*512 + r0)*NS;
    const float* wbase = w2  + (size_t)(i*NF + f0)*NS;
    for (int kc=0; kc<NS; kc+=32){
        for (int idx=tid; idx<64*32; idx+=256){
            int rr = idx>>5, kk = idx&31;
            Xs[rr][kk] = xbase[(size_t)rr*NS + kc+kk]*alpha + beta;
        }
        for (int idx=tid; idx<64*32; idx+=256){
            int ff = idx>>5, kk = idx&31;
            Ws[ff][kk] = wbase[(size_t)ff*NS + kc+kk];
        }
        __syncthreads();
#pragma unroll
        for (int kk=0; kk<32; kk++){
            float a[4], bb[4];
#pragma unroll
            for (int u=0;u<4;u++) a[u]  = Xs[ty*4+u][kk];
#pragma unroll
            for (int v=0;v<4;v++) bb[v] = Ws[tx*4+v][kk];
#pragma unroll
            for (int u=0;u<4;u++)
#pragma unroll
                for (int v=0;v<4;v++) acc[u][v] = fmaf(a[u], bb[v], acc[u][v]);
        }
        __syncthreads();
    }
#pragma unroll
    for (int u=0;u<4;u++){
        int r = r0 + ty*4 + u;
#pragma unroll
        for (int v=0;v<4;v++){
            int f = f0 + tx*4 + v;
            d_u[(size_t)(i*512 + r)*NF + f] = acc[u][v] + b2[i*NF + f];
        }
    }
}

// ---------------- bn2 stats (per-feature mean/var over 512 rows)
__global__ void k_bn2(){
    const int i = blockIdx.y, f0 = blockIdx.x*64;
    const int tid = threadIdx.x, fx = tid&63, rg = tid>>6;
    const float* p = d_u + (size_t)i*512*NF + f0 + fx;
    float s=0.f, sq=0.f;
    for (int r=rg; r<512; r+=4){ float v = p[(size_t)r*NF]; s+=v; sq+=v*v; }
    __shared__ float ss[256], sqs[256];
    ss[tid]=s; sqs[tid]=sq; __syncthreads();
    if (rg==0){
        float S  = ss[fx]  + ss[fx+64]  + ss[fx+128]  + ss[fx+192];
        float SQ = sqs[fx] + sqs[fx+64] + sqs[fx+128] + sqs[fx+192];
        float mean = S/512.f;
        float var  = SQ/512.f - mean*mean;
        d_bn2m[i*NF+f0+fx] = mean;
        d_bn2r[i*NF+f0+fx] = rsqrtf(var + EPSF);
    }
}

// ---------------- fc3: y[row] = relu(bn2(u[row])) . w3   (one warp per row)
__global__ void k_fc3(const float* __restrict__ g2, const float* __restrict__ bb2,
                      const float* __restrict__ w3){
    const int row  = blockIdx.x*8 + (threadIdx.x>>5);   // 512 blocks x 8 warps = 4096 rows
    const int lane = threadIdx.x & 31;
    const int i = row >> 9;
    const float* up = d_u + (size_t)row*NF;
    float s = 0.f;
    for (int f=lane; f<NF; f+=32){
        int gi = i*NF + f;
        float z = g2[gi]*(up[f]-d_bn2m[gi])*d_bn2r[gi] + bb2[gi];
        z = fmaxf(z, 0.f);
        s = fmaf(z, w3[gi], s);
    }
#pragma unroll
    for (int off=16; off; off>>=1) s += __shfl_xor_sync(0xffffffffu, s, off);
    if (lane==0) d_y[row] = s;
}

// ---------------- final: pair-sum, bn3 per layer, accumulate, labels
__global__ void k_final(const float* __restrict__ b3, const float* __restrict__ g3,
                        const float* __restrict__ bb3, const int* __restrict__ targets,
                        float* __restrict__ out, int out_size){
    const int qk = threadIdx.x;   // 256
    __shared__ double ss[256], sqs[256];
    float accum = 0.f;
    for (int i=0;i<NL;i++){
        float p = d_y[i*512 + 2*qk] + d_y[i*512 + 2*qk + 1] + 2.f*b3[i];
        ss[qk] = (double)p; sqs[qk] = (double)p*(double)p;
        __syncthreads();
        for (int off=128; off; off>>=1){
            if (qk<off){ ss[qk]+=ss[qk+off]; sqs[qk]+=sqs[qk+off]; }
            __syncthreads();
        }
        double mean = ss[0]/256.0;
        double var  = sqs[0]/256.0 - mean*mean;
        float rstd  = (float)rsqrt(var + 1e-5);
        accum += g3[i]*((p - (float)mean)*rstd) + bb3[i];
        __syncthreads();   // protect ss/sqs before next layer overwrites
    }
    out[qk] = accum;
    if (out_size >= 512){
        int qq = qk >> 4, kk = qk & 15;
        out[256 + qk] = (targets[qq]==targets[kk]) ? 1.f : 0.f;
    }
}

// ---------------- launcher ----------------
extern "C" void kernel_launch(void* const* d_in, const int* in_sizes, int n_in,
                              void* d_out, int out_size){
    const float* q_feat = (const float*)d_in[0];
    const float* g_feat = (const float*)d_in[1];
    const int*   targets= (const int*)  d_in[2];
    const float* se     = (const float*)d_in[3];
    const float* fc0w   = (const float*)d_in[4];
    const float* fc0b   = (const float*)d_in[5];
    const float* bn1g   = (const float*)d_in[6];
    const float* bn1b   = (const float*)d_in[7];
    const float* fc2w   = (const float*)d_in[8];
    const float* fc2b   = (const float*)d_in[9];
    const float* bn2g   = (const float*)d_in[10];
    const float* bn2b   = (const float*)d_in[11];
    const float* fc3w   = (const float*)d_in[12];
    const float* fc3b   = (const float*)d_in[13];
    const float* bn3g   = (const float*)d_in[14];
    const float* bn3b   = (const float*)d_in[15];
    float* out = (float*)d_out;

    uint32_t *p_qfp, *p_gfp, *p_w0p, *p_qryp, *p_keyp;
    cudaGetSymbolAddress((void**)&p_qfp,  d_qfp);
    cudaGetSymbolAddress((void**)&p_gfp,  d_gfp);
    cudaGetSymbolAddress((void**)&p_w0p,  d_w0p);
    cudaGetSymbolAddress((void**)&p_qryp, d_qryp);
    cudaGetSymbolAddress((void**)&p_keyp, d_keyp);

    const int nfeat = NB*NL*ND*NS;
    const int nw0   = NL*ND*ND;

    k_sigse<<<(NL*NS*NS+255)/256, 256>>>(se);
    k_split<<<(nfeat+255)/256, 256>>>(q_feat, p_qfp, nfeat);
    k_split<<<(nfeat+255)/256, 256>>>(g_feat, p_gfp, nfeat);
    k_split<<<(nw0+255)/256,   256>>>(fc0w,   p_w0p, nw0);
    k_proj<<<dim3(8, NB, NL), 256>>>(p_qfp, fc0b, p_qryp);
    k_proj<<<dim3(8, NB, NL), 256>>>(p_gfp, fc0b, p_keyp);
    k_score<<<dim3(2, 256, NL), 256>>>();
    k_rowmerge<<<(NL*256*NS+255)/256, 256>>>();
    k_bn1<<<NL, 512>>>();
    k_fc2<<<dim3(32, 8, NL), 256>>>(fc2w, fc2b, bn1g, bn1b);
    k_bn2<<<dim3(32, NL), 256>>>();
    k_fc3<<<512, 256>>>(bn2g, bn2b, fc3w);
    k_final<<<1, 256>>>(fc3b, bn3g, bn3b, targets, out, out_size);
}

// round 13
// speedup vs baseline: 2.9461x; 1.5249x over previous
#include <cuda_runtime.h>
#include <cuda_bf16.h>
#include <math.h>
#include <stdint.h>

#define NL 8
#define NS 192
#define ND 512
#define NF 2048
#define NB 16
#define EPSF 1e-5f

// ---------------- scratch (static device globals; no allocations) ----------------
__device__ uint32_t d_qfp  [NB*NL*ND*NS];      // packed bf16(hi,lo) q_feat  [b][i*D+d][t]
__device__ uint32_t d_gfp  [NB*NL*ND*NS];      // packed g_feat
__device__ uint32_t d_w0p  [NL*ND*ND];         // packed fc0_w   [i][e][d]
__device__ uint32_t d_qryp [NL*NB*NS*ND];      // packed query   [i][b][t][e]
__device__ uint32_t d_keyp [NL*NB*NS*ND];      // packed key     [i][b][s][e]
__device__ float d_sigse[NL*NS*NS];            // sigmoid(score_embed)
__device__ float d_x    [NL*512*NS];           // [i][r=2qk+branch][S]
__device__ float d_rowp [NL*256*2*NS];         // rowmax partials (2 s-halves)
__device__ float d_bn1m[NL], d_bn1r[NL];
__device__ float d_u    [NL*512*NF];           // fc2 output
__device__ float d_bn2m[NL*NF], d_bn2r[NL*NF];
__device__ float d_y    [NL*512];              // fc3 per-row output

// ---------------- bf16 split-pack helpers ----------------
// pack x ~= hi + lo (both bf16): low16 = hi, high16 = lo.
// 2-pass mma: pass1 A=(hi,lo) x B=(hi,hi) -> hiA*hiB + loA*hiB
//             pass2 A=(hi,hi) x B=(lo,0)  -> hiA*loB   (drops only loA*loB ~2^-18)
__device__ __forceinline__ uint32_t packsplit(float x){
    __nv_bfloat16 h = __float2bfloat16(x);
    float r = x - __bfloat162float(h);
    __nv_bfloat16 l = __float2bfloat16(r);
    return (uint32_t)__bfloat16_as_ushort(h) | ((uint32_t)__bfloat16_as_ushort(l) << 16);
}
__device__ __forceinline__ uint32_t duphi(uint32_t p){ return __byte_perm(p, p, 0x1010); } // (hi,hi)
__device__ __forceinline__ uint32_t lozero(uint32_t p){ return __byte_perm(p, 0, 0x4432); } // (lo,0)

__device__ __forceinline__ void mma_bf16(float* c, const uint32_t* a, const uint32_t* b){
    asm volatile("mma.sync.aligned.m16n8k16.row.col.f32.bf16.bf16.f32 "
        "{%0,%1,%2,%3}, {%4,%5,%6,%7}, {%8,%9}, {%0,%1,%2,%3};"
        : "+f"(c[0]),"+f"(c[1]),"+f"(c[2]),"+f"(c[3])
        : "r"(a[0]),"r"(a[1]),"r"(a[2]),"r"(a[3]), "r"(b[0]),"r"(b[1]));
}

// cp.async helpers (16B)
__device__ __forceinline__ void cpasync16(void* smem_dst, const void* gmem_src){
    uint32_t sa = (uint32_t)__cvta_generic_to_shared(smem_dst);
    asm volatile("cp.async.cg.shared.global [%0], [%1], 16;" :: "r"(sa), "l"(gmem_src));
}
__device__ __forceinline__ void cpasync_commit(){ asm volatile("cp.async.commit_group;"); }
__device__ __forceinline__ void cpasync_wait1(){ asm volatile("cp.async.wait_group 1;"); }
__device__ __forceinline__ void cpasync_wait0(){ asm volatile("cp.async.wait_group 0;"); }

// ---------------- elementwise split-pack ----------------
__global__ void k_split(const float* __restrict__ src, uint32_t* __restrict__ dst, int n){
    int idx = blockIdx.x*256 + threadIdx.x;
    if (idx < n) dst[idx] = packsplit(src[idx]);
}

// ---------------- precompute sigmoid(score_embed) ----------------
__global__ void k_sigse(const float* __restrict__ se){
    int idx = blockIdx.x*256 + threadIdx.x;
    if (idx < NL*NS*NS) d_sigse[idx] = 1.f/(1.f+expf(-se[idx]));
}

// ---------------- fc0 projection (2-pass bf16-split mma, cp.async double-buffered)
// out[i][b][t][e] = sum_d feat[b][i*D+d][t] * w0[i][e][d] + b0[i][e]
// grid (8 e-tiles, B, L), 256 threads (8 warps). CTA: 192 t x 64 e, 16 elems/chunk.
#define PAS 200
__global__ void __launch_bounds__(256) k_proj(const uint32_t* __restrict__ featP,
                       const float* __restrict__ b0, uint32_t* __restrict__ outP){
    const int i = blockIdx.z, b = blockIdx.y, e0 = blockIdx.x*64;
    const int tid = threadIdx.x;
    const int w = tid>>5, lane = tid&31;
    const int g = lane>>2, c = lane&3;
    const int mw = w>>1, nw = w&1;
    __shared__ uint32_t As[2][16*PAS];   // [kk][t]
    __shared__ uint32_t Bs[2][64*20];    // [e][kk]
    float acc[3][4][4];
#pragma unroll
    for (int mt=0;mt<3;mt++)
#pragma unroll
        for (int nt=0;nt<4;nt++)
#pragma unroll
            for (int r=0;r<4;r++) acc[mt][nt][r]=0.f;
    const uint32_t* fbase = featP + (size_t)(b*(ND*NL) + i*ND)*NS;
    const uint32_t* wbase = d_w0p + (size_t)i*ND*ND + (size_t)e0*ND;
    const int tb = mw*48;

    // stage(ch, buf): As 16x192 (48 chunks/row... 12 uint4 per kk-row), Bs 64x16
    auto stage = [&](int ch, int bufi){
        const int kc = ch*16;
        // As: 16 kk-rows x 12 uint4 = 192 items ; Bs: 64 e-rows x 4 uint4 = 256 items
        for (int idx = tid; idx < 192 + 256; idx += 256){
            if (idx < 192){
                int kk = idx / 12, j = idx % 12;           // j*16 t-offset... j*4 uint32
                cpasync16(&As[bufi][kk*PAS + j*16], &fbase[(size_t)(kc+kk)*NS + j*16]);
            } else {
                int r2 = idx - 192;
                int ee = r2 >> 2, j = r2 & 3;
                cpasync16(&Bs[bufi][ee*20 + j*4], &wbase[(size_t)ee*ND + kc + j*4]);
            }
        }
        cpasync_commit();
    };
    // NOTE: As rows are 192 uint32 = 48 uint4; staged as 12 uint4 of 16B = 12*4 = 48 uint32? No:
    // 12 chunks x 16 uint32? Fix: 192 uint32 per row = 48 x uint4. Use 48 chunks/row.
    // (lambda above replaced below — see stageA full version)

    auto stageFull = [&](int ch, int bufi){
        const int kc = ch*16;
        // As: 16 rows x 48 uint4 = 768 ; Bs: 64 rows x 4 uint4 = 256 ; total 1024
        for (int idx = tid; idx < 1024; idx += 256){
            if (idx < 768){
                int kk = idx / 48, j = idx % 48;
                cpasync16(&As[bufi][kk*PAS + j*4], &fbase[(size_t)(kc+kk)*NS + j*4]);
            } else {
                int r2 = idx - 768;
                int ee = r2 >> 2, j = r2 & 3;
                cpasync16(&Bs[bufi][ee*20 + j*4], &wbase[(size_t)ee*ND + kc + j*4]);
            }
        }
        cpasync_commit();
    };
    (void)stage;

    stageFull(0, 0);
    const int NCH = ND/16;  // 32
    for (int ch = 0; ch < NCH; ch++){
        if (ch + 1 < NCH){ stageFull(ch+1, (ch+1)&1); cpasync_wait1(); }
        else             { cpasync_wait0(); }
        __syncthreads();
        const uint32_t* Ab = As[ch&1];
        const uint32_t* Bb = Bs[ch&1];
#pragma unroll
        for (int ks=0; ks<2; ks++){
            const int k0 = ks*8;
            uint32_t bdup[4][2], blo0[4][2];
#pragma unroll
            for (int nt=0;nt<4;nt++){
                int e = nw*32 + nt*8 + g;
                uint32_t b0r = Bb[e*20 + k0 + c];
                uint32_t b1r = Bb[e*20 + k0 + 4 + c];
                bdup[nt][0] = duphi(b0r);  bdup[nt][1] = duphi(b1r);
                blo0[nt][0] = lozero(b0r); blo0[nt][1] = lozero(b1r);
            }
#pragma unroll
            for (int mt=0;mt<3;mt++){
                int r = tb + mt*16 + g;
                uint32_t araw[4], adup[4];
                araw[0] = Ab[(k0+c)*PAS + r];
                araw[1] = Ab[(k0+c)*PAS + r + 8];
                araw[2] = Ab[(k0+4+c)*PAS + r];
                araw[3] = Ab[(k0+4+c)*PAS + r + 8];
#pragma unroll
                for (int j=0;j<4;j++) adup[j] = duphi(araw[j]);
#pragma unroll
                for (int nt=0;nt<4;nt++){
                    mma_bf16(acc[mt][nt], araw, bdup[nt]);
                    mma_bf16(acc[mt][nt], adup, blo0[nt]);
                }
            }
        }
        __syncthreads();
    }
    // epilogue: + bias, split-pack, store 2 packed elems as uint2
    uint32_t* obase = outP + (size_t)(i*NB+b)*NS*ND;
#pragma unroll
    for (int nt=0;nt<4;nt++){
        int e = e0 + nw*32 + nt*8 + 2*c;
        float b01 = b0[i*ND + e], b11 = b0[i*ND + e + 1];
#pragma unroll
        for (int mt=0;mt<3;mt++){
            int r = tb + mt*16 + g;
            uint2 v0 = make_uint2(packsplit(acc[mt][nt][0] + b01), packsplit(acc[mt][nt][1] + b11));
            uint2 v1 = make_uint2(packsplit(acc[mt][nt][2] + b01), packsplit(acc[mt][nt][3] + b11));
            *reinterpret_cast<uint2*>(&obase[(size_t)r*ND + e])     = v0;
            *reinterpret_cast<uint2*>(&obase[(size_t)(r+8)*ND + e]) = v1;
        }
    }
}

// ---------------- score GEMM (2-pass bf16-split, cp.async double-buffered) + mask + max pooling
// grid (2 s-halves, 256 qk, L), 256 threads (8 warps). CTA: M = t 192 (full q) x N = s 96.
// colmax (over t) direct write; rowmax (over s) -> 2 partials merged by k_rowmerge.
// Reduction scratch (rowbuf/colbuf) ALIASES As[0] — only used after the mainloop.
__global__ void __launch_bounds__(256) k_score(){
    const int i = blockIdx.z, qk = blockIdx.y, sh = blockIdx.x;
    const int q = qk >> 4, k = qk & 15;
    const int s0 = sh*96;
    const int tid = threadIdx.x;
    const int w = tid>>5, lane = tid&31;
    const int g = lane>>2, c = lane&3;
    const int mw = w>>1, nw = w&1;
    __shared__ uint32_t As[2][NS*20];    // query [t][kk]   (2 x 15360B)
    __shared__ uint32_t Bs[2][96*20];    // key   [s][kk]   (2 x 7680B)  total 46KB
    float acc[3][6][4];
#pragma unroll
    for (int mt=0;mt<3;mt++)
#pragma unroll
        for (int nt=0;nt<6;nt++)
#pragma unroll
            for (int r=0;r<4;r++) acc[mt][nt][r]=0.f;
    const uint32_t* qbase = d_qryp + (size_t)(i*NB+q)*NS*ND;
    const uint32_t* kbase = d_keyp + (size_t)(i*NB+k)*NS*ND + (size_t)s0*ND;
    const int tb = mw*48, sb = nw*48;

    auto stage = [&](int ch, int bufi){
        const int kc = ch*16;
        // As: 192 rows x 4 uint4 = 768 ; Bs: 96 rows x 4 uint4 = 384 ; total 1152
        for (int idx = tid; idx < 1152; idx += 256){
            if (idx < 768){
                int t = idx >> 2, j = idx & 3;
                cpasync16(&As[bufi][t*20 + j*4], &qbase[(size_t)t*ND + kc + j*4]);
            } else {
                int r2 = idx - 768;
                int s = r2 >> 2, j = r2 & 3;
                cpasync16(&Bs[bufi][s*20 + j*4], &kbase[(size_t)s*ND + kc + j*4]);
            }
        }
        cpasync_commit();
    };

    stage(0, 0);
    const int NCH = ND/16;  // 32
    for (int ch = 0; ch < NCH; ch++){
        if (ch + 1 < NCH){ stage(ch+1, (ch+1)&1); cpasync_wait1(); }
        else             { cpasync_wait0(); }
        __syncthreads();
        const uint32_t* Ab = As[ch&1];
        const uint32_t* Bb = Bs[ch&1];
#pragma unroll
        for (int ks=0; ks<2; ks++){
            const int k0 = ks*8;
            uint32_t bdup[6][2], blo0[6][2];
#pragma unroll
            for (int nt=0;nt<6;nt++){
                int s = sb + nt*8 + g;
                uint32_t b0r = Bb[s*20 + k0 + c];
                uint32_t b1r = Bb[s*20 + k0 + 4 + c];
                bdup[nt][0] = duphi(b0r);  bdup[nt][1] = duphi(b1r);
                blo0[nt][0] = lozero(b0r); blo0[nt][1] = lozero(b1r);
            }
#pragma unroll
            for (int mt=0;mt<3;mt++){
                int t = tb + mt*16 + g;
                uint32_t araw[4], adup[4];
                araw[0] = Ab[t*20 + k0 + c];
                araw[1] = Ab[(t+8)*20 + k0 + c];
                araw[2] = Ab[t*20 + k0 + 4 + c];
                araw[3] = Ab[(t+8)*20 + k0 + 4 + c];
#pragma unroll
                for (int j=0;j<4;j++) adup[j] = duphi(araw[j]);
#pragma unroll
                for (int nt=0;nt<6;nt++){
                    mma_bf16(acc[mt][nt], araw, bdup[nt]);
                    mma_bf16(acc[mt][nt], adup, blo0[nt]);
                }
            }
        }
        __syncthreads();
    }
    // mask by sigmoid(score_embed): element (row=t, col=s) *= sigse[s*NS + t]
    const float* sbase = d_sigse + (size_t)i*NS*NS;
#pragma unroll
    for (int mt=0;mt<3;mt++){
        int t0v = tb + mt*16 + g, t1v = t0v + 8;
#pragma unroll
        for (int nt=0;nt<6;nt++){
            int sc = s0 + sb + nt*8 + 2*c;
            acc[mt][nt][0] *= sbase[(size_t)sc*NS + t0v];
            acc[mt][nt][1] *= sbase[(size_t)(sc+1)*NS + t0v];
            acc[mt][nt][2] *= sbase[(size_t)sc*NS + t1v];
            acc[mt][nt][3] *= sbase[(size_t)(sc+1)*NS + t1v];
        }
    }
    // reduction scratch aliases As (mainloop done; last barrier passed)
    float* rowbuf = reinterpret_cast<float*>(&As[0][0]);   // [8][48]
    float* colbuf = rowbuf + 8*48;                          // [8][48]
    // ---- rowmax partial: max over this CTA's 96 s, per t row ----
    float rm[3][2];
#pragma unroll
    for (int mt=0;mt<3;mt++){
        float m0 = fmaxf(acc[mt][0][0], acc[mt][0][1]);
        float m1 = fmaxf(acc[mt][0][2], acc[mt][0][3]);
#pragma unroll
        for (int nt=1;nt<6;nt++){
            m0 = fmaxf(m0, fmaxf(acc[mt][nt][0], acc[mt][nt][1]));
            m1 = fmaxf(m1, fmaxf(acc[mt][nt][2], acc[mt][nt][3]));
        }
        rm[mt][0] = m0; rm[mt][1] = m1;
    }
#pragma unroll
    for (int off=1; off<4; off<<=1)
#pragma unroll
        for (int mt=0;mt<3;mt++){
            rm[mt][0] = fmaxf(rm[mt][0], __shfl_xor_sync(0xffffffffu, rm[mt][0], off));
            rm[mt][1] = fmaxf(rm[mt][1], __shfl_xor_sync(0xffffffffu, rm[mt][1], off));
        }
    if (c == 0){
#pragma unroll
        for (int mt=0;mt<3;mt++){
            rowbuf[w*48 + mt*16 + g]     = rm[mt][0];
            rowbuf[w*48 + mt*16 + g + 8] = rm[mt][1];
        }
    }
    // ---- colmax: max over all 192 t (full in CTA), per s col ----
    float cm[6][2];
#pragma unroll
    for (int nt=0;nt<6;nt++){
        float m0 = fmaxf(acc[0][nt][0], acc[0][nt][2]);
        float m1 = fmaxf(acc[0][nt][1], acc[0][nt][3]);
#pragma unroll
        for (int mt=1;mt<3;mt++){
            m0 = fmaxf(m0, fmaxf(acc[mt][nt][0], acc[mt][nt][2]));
            m1 = fmaxf(m1, fmaxf(acc[mt][nt][1], acc[mt][nt][3]));
        }
        cm[nt][0] = m0; cm[nt][1] = m1;
    }
#pragma unroll
    for (int off=4; off<32; off<<=1)
#pragma unroll
        for (int nt=0;nt<6;nt++){
            cm[nt][0] = fmaxf(cm[nt][0], __shfl_xor_sync(0xffffffffu, cm[nt][0], off));
            cm[nt][1] = fmaxf(cm[nt][1], __shfl_xor_sync(0xffffffffu, cm[nt][1], off));
        }
    if (g == 0){
#pragma unroll
        for (int nt=0;nt<6;nt++){
            colbuf[w*48 + nt*8 + 2*c]     = cm[nt][0];
            colbuf[w*48 + nt*8 + 2*c + 1] = cm[nt][1];
        }
    }
    __syncthreads();
    // merge across warps: 192 rowmax entries + 96 colmax entries = 288 items, strided
    for (int idx = tid; idx < NS + 96; idx += 256){
        if (idx < NS){   // rowmax partial: merge 2 n-warps for this t row
            int mwv = idx / 48, j = idx % 48;
            float v = fmaxf(rowbuf[mwv*2*48 + j], rowbuf[(mwv*2+1)*48 + j]);
            d_rowp[(((size_t)i*256 + qk)*2 + sh)*NS + idx] = v;
        } else {         // colmax: merge 4 m-warps, direct write odd row
            int sl = idx - NS;
            int nwv = sl / 48, j = sl % 48;
            float v = colbuf[nwv*48 + j];
#pragma unroll
            for (int mwv=1; mwv<4; mwv++) v = fmaxf(v, colbuf[(mwv*2 + nwv)*48 + j]);
            d_x[((size_t)i*512 + 2*qk + 1)*NS + s0 + sl] = v;
        }
    }
}

// ---------------- merge rowmax partials (2 s-halves) into even rows of x
__global__ void k_rowmerge(){
    int idx = blockIdx.x*256 + threadIdx.x;       // NL*256*NS = 393216
    if (idx >= NL*256*NS) return;
    int t   = idx % NS;
    int iqk = idx / NS;
    int i   = iqk >> 8;
    int qk  = iqk & 255;
    const float* p = d_rowp + (size_t)iqk*2*NS + t;
    d_x[((size_t)i*512 + 2*qk)*NS + t] = fmaxf(p[0], p[NS]);
}

// ---------------- bn1 stats (whole-tensor mean/var per layer), double accum
__global__ void k_bn1(){
    const int i = blockIdx.x, tid = threadIdx.x;   // 8 blocks x 512 threads
    const float* p = d_x + (size_t)i*512*NS;
    double s=0.0, sq=0.0;
    for (int idx=tid; idx<512*NS; idx+=512){ double v = p[idx]; s+=v; sq+=v*v; }
    __shared__ double ss[512], sqs[512];
    ss[tid]=s; sqs[tid]=sq; __syncthreads();
    for (int off=256; off; off>>=1){
        if (tid<off){ ss[tid]+=ss[tid+off]; sqs[tid]+=sqs[tid+off]; }
        __syncthreads();
    }
    if (tid==0){
        double n = 512.0*NS;
        double mean = ss[0]/n;
        double var  = sqs[0]/n - mean*mean;
        d_bn1m[i] = (float)mean;
        d_bn1r[i] = (float)rsqrt(var + 1e-5);
    }
}

// ---------------- fc2: u = bn1(x) @ w2^T + b2.  grid (32 f-tiles, 8 r-tiles, L), 256 thr, CTA 64x64.
__global__ void k_fc2(const float* __restrict__ w2, const float* __restrict__ b2,
                      const float* __restrict__ g1, const float* __restrict__ b1){
    const int i = blockIdx.z, r0 = blockIdx.y*64, f0 = blockIdx.x*64;
    const int tid = threadIdx.x, tx = tid&15, ty = tid>>4;
    const float alpha = g1[i]*d_bn1r[i];
    const float beta  = b1[i] - d_bn1m[i]*alpha;
    __shared__ float Xs[64][33], Ws[64][33];
    float acc[4][4];
#pragma unroll
    for (int u=0;u<4;u++)
#pragma unroll
        for (int v=0;v<4;v++) acc[u][v]=0.f;
    const float* xbase = d_x + (size_t)(i*512 + r0)*NS;
    const float* wbase = w2  + (size_t)(i*NF + f0)*NS;
    for (int kc=0; kc<NS; kc+=32){
        for (int idx=tid; idx<64*32; idx+=256){
            int rr = idx>>5, kk = idx&31;
            Xs[rr][kk] = xbase[(size_t)rr*NS + kc+kk]*alpha + beta;
        }
        for (int idx=tid; idx<64*32; idx+=256){
            int ff = idx>>5, kk = idx&31;
            Ws[ff][kk] = wbase[(size_t)ff*NS + kc+kk];
        }
        __syncthreads();
#pragma unroll
        for (int kk=0; kk<32; kk++){
            float a[4], bb[4];
#pragma unroll
            for (int u=0;u<4;u++) a[u]  = Xs[ty*4+u][kk];
#pragma unroll
            for (int v=0;v<4;v++) bb[v] = Ws[tx*4+v][kk];
#pragma unroll
            for (int u=0;u<4;u++)
#pragma unroll
                for (int v=0;v<4;v++) acc[u][v] = fmaf(a[u], bb[v], acc[u][v]);
        }
        __syncthreads();
    }
#pragma unroll
    for (int u=0;u<4;u++){
        int r = r0 + ty*4 + u;
#pragma unroll
        for (int v=0;v<4;v++){
            int f = f0 + tx*4 + v;
            d_u[(size_t)(i*512 + r)*NF + f] = acc[u][v] + b2[i*NF + f];
        }
    }
}

// ---------------- bn2 stats (per-feature mean/var over 512 rows)
__global__ void k_bn2(){
    const int i = blockIdx.y, f0 = blockIdx.x*64;
    const int tid = threadIdx.x, fx = tid&63, rg = tid>>6;
    const float* p = d_u + (size_t)i*512*NF + f0 + fx;
    float s=0.f, sq=0.f;
    for (int r=rg; r<512; r+=4){ float v = p[(size_t)r*NF]; s+=v; sq+=v*v; }
    __shared__ float ss[256], sqs[256];
    ss[tid]=s; sqs[tid]=sq; __syncthreads();
    if (rg==0){
        float S  = ss[fx]  + ss[fx+64]  + ss[fx+128]  + ss[fx+192];
        float SQ = sqs[fx] + sqs[fx+64] + sqs[fx+128] + sqs[fx+192];
        float mean = S/512.f;
        float var  = SQ/512.f - mean*mean;
        d_bn2m[i*NF+f0+fx] = mean;
        d_bn2r[i*NF+f0+fx] = rsqrtf(var + EPSF);
    }
}

// ---------------- fc3: y[row] = relu(bn2(u[row])) . w3   (one warp per row)
__global__ void k_fc3(const float* __restrict__ g2, const float* __restrict__ bb2,
                      const float* __restrict__ w3){
    const int row  = blockIdx.x*8 + (threadIdx.x>>5);   // 512 blocks x 8 warps = 4096 rows
    const int lane = threadIdx.x & 31;
    const int i = row >> 9;
    const float* up = d_u + (size_t)row*NF;
    float s = 0.f;
    for (int f=lane; f<NF; f+=32){
        int gi = i*NF + f;
        float z = g2[gi]*(up[f]-d_bn2m[gi])*d_bn2r[gi] + bb2[gi];
        z = fmaxf(z, 0.f);
        s = fmaf(z, w3[gi], s);
    }
#pragma unroll
    for (int off=16; off; off>>=1) s += __shfl_xor_sync(0xffffffffu, s, off);
    if (lane==0) d_y[row] = s;
}

// ---------------- final: pair-sum, bn3 per layer, accumulate, labels
__global__ void k_final(const float* __restrict__ b3, const float* __restrict__ g3,
                        const float* __restrict__ bb3, const int* __restrict__ targets,
                        float* __restrict__ out, int out_size){
    const int qk = threadIdx.x;   // 256
    __shared__ double ss[256], sqs[256];
    float accum = 0.f;
    for (int i=0;i<NL;i++){
        float p = d_y[i*512 + 2*qk] + d_y[i*512 + 2*qk + 1] + 2.f*b3[i];
        ss[qk] = (double)p; sqs[qk] = (double)p*(double)p;
        __syncthreads();
        for (int off=128; off; off>>=1){
            if (qk<off){ ss[qk]+=ss[qk+off]; sqs[qk]+=sqs[qk+off]; }
            __syncthreads();
        }
        double mean = ss[0]/256.0;
        double var  = sqs[0]/256.0 - mean*mean;
        float rstd  = (float)rsqrt(var + 1e-5);
        accum += g3[i]*((p - (float)mean)*rstd) + bb3[i];
        __syncthreads();   // protect ss/sqs before next layer overwrites
    }
    out[qk] = accum;
    if (out_size >= 512){
        int qq = qk >> 4, kk = qk & 15;
        out[256 + qk] = (targets[qq]==targets[kk]) ? 1.f : 0.f;
    }
}

// ---------------- launcher ----------------
extern "C" void kernel_launch(void* const* d_in, const int* in_sizes, int n_in,
                              void* d_out, int out_size){
    const float* q_feat = (const float*)d_in[0];
    const float* g_feat = (const float*)d_in[1];
    const int*   targets= (const int*)  d_in[2];
    const float* se     = (const float*)d_in[3];
    const float* fc0w   = (const float*)d_in[4];
    const float* fc0b   = (const float*)d_in[5];
    const float* bn1g   = (const float*)d_in[6];
    const float* bn1b   = (const float*)d_in[7];
    const float* fc2w   = (const float*)d_in[8];
    const float* fc2b   = (const float*)d_in[9];
    const float* bn2g   = (const float*)d_in[10];
    const float* bn2b   = (const float*)d_in[11];
    const float* fc3w   = (const float*)d_in[12];
    const float* fc3b   = (const float*)d_in[13];
    const float* bn3g   = (const float*)d_in[14];
    const float* bn3b   = (const float*)d_in[15];
    float* out = (float*)d_out;

    uint32_t *p_qfp, *p_gfp, *p_w0p, *p_qryp, *p_keyp;
    cudaGetSymbolAddress((void**)&p_qfp,  d_qfp);
    cudaGetSymbolAddress((void**)&p_gfp,  d_gfp);
    cudaGetSymbolAddress((void**)&p_w0p,  d_w0p);
    cudaGetSymbolAddress((void**)&p_qryp, d_qryp);
    cudaGetSymbolAddress((void**)&p_keyp, d_keyp);

    const int nfeat = NB*NL*ND*NS;
    const int nw0   = NL*ND*ND;

    k_sigse<<<(NL*NS*NS+255)/256, 256>>>(se);
    k_split<<<(nfeat+255)/256, 256>>>(q_feat, p_qfp, nfeat);
    k_split<<<(nfeat+255)/256, 256>>>(g_feat, p_gfp, nfeat);
    k_split<<<(nw0+255)/256,   256>>>(fc0w,   p_w0p, nw0);
    k_proj<<<dim3(8, NB, NL), 256>>>(p_qfp, fc0b, p_qryp);
    k_proj<<<dim3(8, NB, NL), 256>>>(p_gfp, fc0b, p_keyp);
    k_score<<<dim3(2, 256, NL), 256>>>();
    k_rowmerge<<<(NL*256*NS+255)/256, 256>>>();
    k_bn1<<<NL, 512>>>();
    k_fc2<<<dim3(32, 8, NL), 256>>>(fc2w, fc2b, bn1g, bn1b);
    k_bn2<<<dim3(32, NL), 256>>>();
    k_fc3<<<512, 256>>>(bn2g, bn2b, fc3w);
    k_final<<<1, 256>>>(fc3b, bn3g, bn3b, targets, out, out_size);
}

// round 14
// speedup vs baseline: 3.1596x; 1.0724x over previous
#include <cuda_runtime.h>
#include <cuda_bf16.h>
#include <math.h>
#include <stdint.h>

#define NL 8
#define NS 192
#define ND 512
#define NF 2048
#define NB 16
#define EPSF 1e-5f

// ---------------- scratch (static device globals; no allocations) ----------------
__device__ uint32_t d_qfp  [NB*NL*ND*NS];      // packed bf16(hi,lo) q_feat  [b][i*D+d][t]
__device__ uint32_t d_gfp  [NB*NL*ND*NS];      // packed g_feat
__device__ uint32_t d_w0p  [NL*ND*ND];         // packed fc0_w   [i][e][d]
__device__ uint32_t d_qryp [NL*NB*NS*ND];      // packed query   [i][b][t][e]
__device__ uint32_t d_keyp [NL*NB*NS*ND];      // packed key     [i][b][s][e]
__device__ float d_sigse[NL*NS*NS];            // sigmoid(score_embed)
__device__ float d_x    [NL*512*NS];           // [i][r=2qk+branch][S]
__device__ float d_bn1m[NL], d_bn1r[NL];
__device__ float d_u    [NL*512*NF];           // fc2 output
__device__ float d_bn2m[NL*NF], d_bn2r[NL*NF];
__device__ float d_y    [NL*512];              // fc3 per-row output

// ---------------- bf16 split-pack helpers ----------------
// pack x ~= hi + lo (both bf16): low16 = hi, high16 = lo.
// 2-pass mma: pass1 A=(hi,lo) x B=(hi,hi) -> hiA*hiB + loA*hiB
//             pass2 A=(hi,hi) x B=(lo,0)  -> hiA*loB   (drops only loA*loB ~2^-18)
__device__ __forceinline__ uint32_t packsplit(float x){
    __nv_bfloat16 h = __float2bfloat16(x);
    float r = x - __bfloat162float(h);
    __nv_bfloat16 l = __float2bfloat16(r);
    return (uint32_t)__bfloat16_as_ushort(h) | ((uint32_t)__bfloat16_as_ushort(l) << 16);
}
__device__ __forceinline__ uint32_t duphi(uint32_t p){ return __byte_perm(p, p, 0x1010); } // (hi,hi)
__device__ __forceinline__ uint32_t lozero(uint32_t p){ return __byte_perm(p, 0, 0x4432); } // (lo,0)

__device__ __forceinline__ void mma_bf16(float* c, const uint32_t* a, const uint32_t* b){
    asm volatile("mma.sync.aligned.m16n8k16.row.col.f32.bf16.bf16.f32 "
        "{%0,%1,%2,%3}, {%4,%5,%6,%7}, {%8,%9}, {%0,%1,%2,%3};"
        : "+f"(c[0]),"+f"(c[1]),"+f"(c[2]),"+f"(c[3])
        : "r"(a[0]),"r"(a[1]),"r"(a[2]),"r"(a[3]), "r"(b[0]),"r"(b[1]));
}

// cp.async helpers (16B)
__device__ __forceinline__ void cpasync16(void* smem_dst, const void* gmem_src){
    uint32_t sa = (uint32_t)__cvta_generic_to_shared(smem_dst);
    asm volatile("cp.async.cg.shared.global [%0], [%1], 16;" :: "r"(sa), "l"(gmem_src));
}
__device__ __forceinline__ void cpasync_commit(){ asm volatile("cp.async.commit_group;"); }
__device__ __forceinline__ void cpasync_wait1(){ asm volatile("cp.async.wait_group 1;"); }
__device__ __forceinline__ void cpasync_wait0(){ asm volatile("cp.async.wait_group 0;"); }

// ---------------- elementwise split-pack ----------------
__global__ void k_split(const float* __restrict__ src, uint32_t* __restrict__ dst, int n){
    int idx = blockIdx.x*256 + threadIdx.x;
    if (idx < n) dst[idx] = packsplit(src[idx]);
}

// ---------------- precompute sigmoid(score_embed) ----------------
__global__ void k_sigse(const float* __restrict__ se){
    int idx = blockIdx.x*256 + threadIdx.x;
    if (idx < NL*NS*NS) d_sigse[idx] = 1.f/(1.f+expf(-se[idx]));
}

// ---------------- fc0 projection (2-pass bf16-split mma, cp.async double-buffered)
// out[i][b][t][e] = sum_d feat[b][i*D+d][t] * w0[i][e][d] + b0[i][e]
// grid (8 e-tiles, B, L), 256 threads (8 warps). CTA: 192 t x 64 e, 16 elems/chunk.
#define PAS 200
__global__ void __launch_bounds__(256) k_proj(const uint32_t* __restrict__ featP,
                       const float* __restrict__ b0, uint32_t* __restrict__ outP){
    const int i = blockIdx.z, b = blockIdx.y, e0 = blockIdx.x*64;
    const int tid = threadIdx.x;
    const int w = tid>>5, lane = tid&31;
    const int g = lane>>2, c = lane&3;
    const int mw = w>>1, nw = w&1;
    __shared__ uint32_t As[2][16*PAS];   // [kk][t]
    __shared__ uint32_t Bs[2][64*20];    // [e][kk]
    float acc[3][4][4];
#pragma unroll
    for (int mt=0;mt<3;mt++)
#pragma unroll
        for (int nt=0;nt<4;nt++)
#pragma unroll
            for (int r=0;r<4;r++) acc[mt][nt][r]=0.f;
    const uint32_t* fbase = featP + (size_t)(b*(ND*NL) + i*ND)*NS;
    const uint32_t* wbase = d_w0p + (size_t)i*ND*ND + (size_t)e0*ND;
    const int tb = mw*48;

    auto stageFull = [&](int ch, int bufi){
        const int kc = ch*16;
        // As: 16 rows x 48 uint4 = 768 ; Bs: 64 rows x 4 uint4 = 256 ; total 1024
        for (int idx = tid; idx < 1024; idx += 256){
            if (idx < 768){
                int kk = idx / 48, j = idx % 48;
                cpasync16(&As[bufi][kk*PAS + j*4], &fbase[(size_t)(kc+kk)*NS + j*4]);
            } else {
                int r2 = idx - 768;
                int ee = r2 >> 2, j = r2 & 3;
                cpasync16(&Bs[bufi][ee*20 + j*4], &wbase[(size_t)ee*ND + kc + j*4]);
            }
        }
        cpasync_commit();
    };

    stageFull(0, 0);
    const int NCH = ND/16;  // 32
    for (int ch = 0; ch < NCH; ch++){
        if (ch + 1 < NCH){ stageFull(ch+1, (ch+1)&1); cpasync_wait1(); }
        else             { cpasync_wait0(); }
        __syncthreads();
        const uint32_t* Ab = As[ch&1];
        const uint32_t* Bb = Bs[ch&1];
#pragma unroll
        for (int ks=0; ks<2; ks++){
            const int k0 = ks*8;
            uint32_t bdup[4][2], blo0[4][2];
#pragma unroll
            for (int nt=0;nt<4;nt++){
                int e = nw*32 + nt*8 + g;
                uint32_t b0r = Bb[e*20 + k0 + c];
                uint32_t b1r = Bb[e*20 + k0 + 4 + c];
                bdup[nt][0] = duphi(b0r);  bdup[nt][1] = duphi(b1r);
                blo0[nt][0] = lozero(b0r); blo0[nt][1] = lozero(b1r);
            }
#pragma unroll
            for (int mt=0;mt<3;mt++){
                int r = tb + mt*16 + g;
                uint32_t araw[4], adup[4];
                araw[0] = Ab[(k0+c)*PAS + r];
                araw[1] = Ab[(k0+c)*PAS + r + 8];
                araw[2] = Ab[(k0+4+c)*PAS + r];
                araw[3] = Ab[(k0+4+c)*PAS + r + 8];
#pragma unroll
                for (int j=0;j<4;j++) adup[j] = duphi(araw[j]);
#pragma unroll
                for (int nt=0;nt<4;nt++){
                    mma_bf16(acc[mt][nt], araw, bdup[nt]);
                    mma_bf16(acc[mt][nt], adup, blo0[nt]);
                }
            }
        }
        __syncthreads();
    }
    // epilogue: + bias, split-pack, store 2 packed elems as uint2
    uint32_t* obase = outP + (size_t)(i*NB+b)*NS*ND;
#pragma unroll
    for (int nt=0;nt<4;nt++){
        int e = e0 + nw*32 + nt*8 + 2*c;
        float b01 = b0[i*ND + e], b11 = b0[i*ND + e + 1];
#pragma unroll
        for (int mt=0;mt<3;mt++){
            int r = tb + mt*16 + g;
            uint2 v0 = make_uint2(packsplit(acc[mt][nt][0] + b01), packsplit(acc[mt][nt][1] + b11));
            uint2 v1 = make_uint2(packsplit(acc[mt][nt][2] + b01), packsplit(acc[mt][nt][3] + b11));
            *reinterpret_cast<uint2*>(&obase[(size_t)r*ND + e])     = v0;
            *reinterpret_cast<uint2*>(&obase[(size_t)(r+8)*ND + e]) = v1;
        }
    }
}

// ---------------- score GEMM (2-pass bf16-split, cp.async 2-stage, K-chunk 32)
// grid (256 qk, L), 512 threads (16 warps). CTA: FULL tile t 192 x s 192.
// warp w: mw=w>>2 -> t-base mw*48 (3 m-tiles), nw=w&3 -> s-base nw*48 (6 n-tiles).
// Both rowmax and colmax complete in-CTA (no partials, no merge kernel).
// Dynamic smem: 2 x (192 As + 192 Bs) x stride 36 x 4B = 110592 B.
#define STR 36
__global__ void __launch_bounds__(512) k_score(){
    extern __shared__ uint32_t dynsm[];
    const int i = blockIdx.y, qk = blockIdx.x;
    const int q = qk >> 4, k = qk & 15;
    const int tid = threadIdx.x;
    const int w = tid>>5, lane = tid&31;
    const int g = lane>>2, c = lane&3;
    const int mw = w>>2, nw = w&3;
    uint32_t* Asb[2] = { dynsm,            dynsm + NS*STR };
    uint32_t* Bsb[2] = { dynsm + 2*NS*STR, dynsm + 3*NS*STR };
    float acc[3][6][4];
#pragma unroll
    for (int mt=0;mt<3;mt++)
#pragma unroll
        for (int nt=0;nt<6;nt++)
#pragma unroll
            for (int r=0;r<4;r++) acc[mt][nt][r]=0.f;
    const uint32_t* qbase = d_qryp + (size_t)(i*NB+q)*NS*ND;
    const uint32_t* kbase = d_keyp + (size_t)(i*NB+k)*NS*ND;
    const int tb = mw*48, sb = nw*48;

    auto stage = [&](int ch, int bufi){
        const int kc = ch*32;
        // As: 192 rows x 8 uint4 = 1536 ; Bs same ; total 3072
        for (int idx = tid; idx < 3072; idx += 512){
            if (idx < 1536){
                int t = idx >> 3, j = idx & 7;
                cpasync16(&Asb[bufi][t*STR + j*4], &qbase[(size_t)t*ND + kc + j*4]);
            } else {
                int r2 = idx - 1536;
                int s = r2 >> 3, j = r2 & 7;
                cpasync16(&Bsb[bufi][s*STR + j*4], &kbase[(size_t)s*ND + kc + j*4]);
            }
        }
        cpasync_commit();
    };

    stage(0, 0);
    const int NCH = ND/32;  // 16
    for (int ch = 0; ch < NCH; ch++){
        if (ch + 1 < NCH){ stage(ch+1, (ch+1)&1); cpasync_wait1(); }
        else             { cpasync_wait0(); }
        __syncthreads();
        const uint32_t* Ab = Asb[ch&1];
        const uint32_t* Bb = Bsb[ch&1];
#pragma unroll
        for (int ks=0; ks<4; ks++){
            const int k0 = ks*8;
            uint32_t bdup[6][2], blo0[6][2];
#pragma unroll
            for (int nt=0;nt<6;nt++){
                int s = sb + nt*8 + g;
                uint32_t b0r = Bb[s*STR + k0 + c];
                uint32_t b1r = Bb[s*STR + k0 + 4 + c];
                bdup[nt][0] = duphi(b0r);  bdup[nt][1] = duphi(b1r);
                blo0[nt][0] = lozero(b0r); blo0[nt][1] = lozero(b1r);
            }
#pragma unroll
            for (int mt=0;mt<3;mt++){
                int t = tb + mt*16 + g;
                uint32_t araw[4], adup[4];
                araw[0] = Ab[t*STR + k0 + c];
                araw[1] = Ab[(t+8)*STR + k0 + c];
                araw[2] = Ab[t*STR + k0 + 4 + c];
                araw[3] = Ab[(t+8)*STR + k0 + 4 + c];
#pragma unroll
                for (int j=0;j<4;j++) adup[j] = duphi(araw[j]);
#pragma unroll
                for (int nt=0;nt<6;nt++){
                    mma_bf16(acc[mt][nt], araw, bdup[nt]);
                    mma_bf16(acc[mt][nt], adup, blo0[nt]);
                }
            }
        }
        __syncthreads();
    }
    // mask by sigmoid(score_embed): element (row=t, col=s) *= sigse[s*NS + t]
    const float* sbase = d_sigse + (size_t)i*NS*NS;
#pragma unroll
    for (int mt=0;mt<3;mt++){
        int t0v = tb + mt*16 + g, t1v = t0v + 8;
#pragma unroll
        for (int nt=0;nt<6;nt++){
            int sc = sb + nt*8 + 2*c;
            acc[mt][nt][0] *= sbase[(size_t)sc*NS + t0v];
            acc[mt][nt][1] *= sbase[(size_t)(sc+1)*NS + t0v];
            acc[mt][nt][2] *= sbase[(size_t)sc*NS + t1v];
            acc[mt][nt][3] *= sbase[(size_t)(sc+1)*NS + t1v];
        }
    }
    // reduction scratch aliases dynsm (mainloop done; 6KB << As[0]'s 27.6KB; As[1]/Bs untouched)
    float* rowbuf = reinterpret_cast<float*>(dynsm);        // [16][48]
    float* colbuf = rowbuf + 16*48;                          // [16][48]
    // ---- rowmax partial: per warp, max over its 48 s, per t row ----
    float rm[3][2];
#pragma unroll
    for (int mt=0;mt<3;mt++){
        float m0 = fmaxf(acc[mt][0][0], acc[mt][0][1]);
        float m1 = fmaxf(acc[mt][0][2], acc[mt][0][3]);
#pragma unroll
        for (int nt=1;nt<6;nt++){
            m0 = fmaxf(m0, fmaxf(acc[mt][nt][0], acc[mt][nt][1]));
            m1 = fmaxf(m1, fmaxf(acc[mt][nt][2], acc[mt][nt][3]));
        }
        rm[mt][0] = m0; rm[mt][1] = m1;
    }
#pragma unroll
    for (int off=1; off<4; off<<=1)
#pragma unroll
        for (int mt=0;mt<3;mt++){
            rm[mt][0] = fmaxf(rm[mt][0], __shfl_xor_sync(0xffffffffu, rm[mt][0], off));
            rm[mt][1] = fmaxf(rm[mt][1], __shfl_xor_sync(0xffffffffu, rm[mt][1], off));
        }
    if (c == 0){
#pragma unroll
        for (int mt=0;mt<3;mt++){
            rowbuf[w*48 + mt*16 + g]     = rm[mt][0];
            rowbuf[w*48 + mt*16 + g + 8] = rm[mt][1];
        }
    }
    // ---- colmax partial: per warp, max over its 48 t, per s col ----
    float cm[6][2];
#pragma unroll
    for (int nt=0;nt<6;nt++){
        float m0 = fmaxf(acc[0][nt][0], acc[0][nt][2]);
        float m1 = fmaxf(acc[0][nt][1], acc[0][nt][3]);
#pragma unroll
        for (int mt=1;mt<3;mt++){
            m0 = fmaxf(m0, fmaxf(acc[mt][nt][0], acc[mt][nt][2]));
            m1 = fmaxf(m1, fmaxf(acc[mt][nt][1], acc[mt][nt][3]));
        }
        cm[nt][0] = m0; cm[nt][1] = m1;
    }
#pragma unroll
    for (int off=4; off<32; off<<=1)
#pragma unroll
        for (int nt=0;nt<6;nt++){
            cm[nt][0] = fmaxf(cm[nt][0], __shfl_xor_sync(0xffffffffu, cm[nt][0], off));
            cm[nt][1] = fmaxf(cm[nt][1], __shfl_xor_sync(0xffffffffu, cm[nt][1], off));
        }
    if (g == 0){
#pragma unroll
        for (int nt=0;nt<6;nt++){
            colbuf[w*48 + nt*8 + 2*c]     = cm[nt][0];
            colbuf[w*48 + nt*8 + 2*c + 1] = cm[nt][1];
        }
    }
    __syncthreads();
    // final merge: 192 rowmax (over 4 n-warps) + 192 colmax (over 4 m-warps), both direct writes
    for (int idx = tid; idx < 2*NS; idx += 512){
        if (idx < NS){       // rowmax for t row idx: warps w = mw*4 + nw, nw 0..3
            int mwv = idx / 48, j = idx % 48;
            float v = rowbuf[(mwv*4 + 0)*48 + j];
#pragma unroll
            for (int nwv=1; nwv<4; nwv++) v = fmaxf(v, rowbuf[(mwv*4 + nwv)*48 + j]);
            d_x[((size_t)i*512 + 2*qk)*NS + idx] = v;
        } else {             // colmax for s col: warps w = mw*4 + nw, mw 0..3
            int sl = idx - NS;
            int nwv = sl / 48, j = sl % 48;
            float v = colbuf[(0*4 + nwv)*48 + j];
#pragma unroll
            for (int mwv=1; mwv<4; mwv++) v = fmaxf(v, colbuf[(mwv*4 + nwv)*48 + j]);
            d_x[((size_t)i*512 + 2*qk + 1)*NS + sl] = v;
        }
    }
}

// ---------------- bn1 stats (whole-tensor mean/var per layer), double accum
__global__ void k_bn1(){
    const int i = blockIdx.x, tid = threadIdx.x;   // 8 blocks x 512 threads
    const float* p = d_x + (size_t)i*512*NS;
    double s=0.0, sq=0.0;
    for (int idx=tid; idx<512*NS; idx+=512){ double v = p[idx]; s+=v; sq+=v*v; }
    __shared__ double ss[512], sqs[512];
    ss[tid]=s; sqs[tid]=sq; __syncthreads();
    for (int off=256; off; off>>=1){
        if (tid<off){ ss[tid]+=ss[tid+off]; sqs[tid]+=sqs[tid+off]; }
        __syncthreads();
    }
    if (tid==0){
        double n = 512.0*NS;
        double mean = ss[0]/n;
        double var  = sqs[0]/n - mean*mean;
        d_bn1m[i] = (float)mean;
        d_bn1r[i] = (float)rsqrt(var + 1e-5);
    }
}

// ---------------- fc2: u = bn1(x) @ w2^T + b2.  grid (32 f-tiles, 8 r-tiles, L), 256 thr, CTA 64x64.
__global__ void k_fc2(const float* __restrict__ w2, const float* __restrict__ b2,
                      const float* __restrict__ g1, const float* __restrict__ b1){
    const int i = blockIdx.z, r0 = blockIdx.y*64, f0 = blockIdx.x*64;
    const int tid = threadIdx.x, tx = tid&15, ty = tid>>4;
    const float alpha = g1[i]*d_bn1r[i];
    const float beta  = b1[i] - d_bn1m[i]*alpha;
    __shared__ float Xs[64][33], Ws[64][33];
    float acc[4][4];
#pragma unroll
    for (int u=0;u<4;u++)
#pragma unroll
        for (int v=0;v<4;v++) acc[u][v]=0.f;
    const float* xbase = d_x + (size_t)(i*512 + r0)*NS;
    const float* wbase = w2  + (size_t)(i*NF + f0)*NS;
    for (int kc=0; kc<NS; kc+=32){
        for (int idx=tid; idx<64*32; idx+=256){
            int rr = idx>>5, kk = idx&31;
            Xs[rr][kk] = xbase[(size_t)rr*NS + kc+kk]*alpha + beta;
        }
        for (int idx=tid; idx<64*32; idx+=256){
            int ff = idx>>5, kk = idx&31;
            Ws[ff][kk] = wbase[(size_t)ff*NS + kc+kk];
        }
        __syncthreads();
#pragma unroll
        for (int kk=0; kk<32; kk++){
            float a[4], bb[4];
#pragma unroll
            for (int u=0;u<4;u++) a[u]  = Xs[ty*4+u][kk];
#pragma unroll
            for (int v=0;v<4;v++) bb[v] = Ws[tx*4+v][kk];
#pragma unroll
            for (int u=0;u<4;u++)
#pragma unroll
                for (int v=0;v<4;v++) acc[u][v] = fmaf(a[u], bb[v], acc[u][v]);
        }
        __syncthreads();
    }
#pragma unroll
    for (int u=0;u<4;u++){
        int r = r0 + ty*4 + u;
#pragma unroll
        for (int v=0;v<4;v++){
            int f = f0 + tx*4 + v;
            d_u[(size_t)(i*512 + r)*NF + f] = acc[u][v] + b2[i*NF + f];
        }
    }
}

// ---------------- bn2 stats (per-feature mean/var over 512 rows)
__global__ void k_bn2(){
    const int i = blockIdx.y, f0 = blockIdx.x*64;
    const int tid = threadIdx.x, fx = tid&63, rg = tid>>6;
    const float* p = d_u + (size_t)i*512*NF + f0 + fx;
    float s=0.f, sq=0.f;
    for (int r=rg; r<512; r+=4){ float v = p[(size_t)r*NF]; s+=v; sq+=v*v; }
    __shared__ float ss[256], sqs[256];
    ss[tid]=s; sqs[tid]=sq; __syncthreads();
    if (rg==0){
        float S  = ss[fx]  + ss[fx+64]  + ss[fx+128]  + ss[fx+192];
        float SQ = sqs[fx] + sqs[fx+64] + sqs[fx+128] + sqs[fx+192];
        float mean = S/512.f;
        float var  = SQ/512.f - mean*mean;
        d_bn2m[i*NF+f0+fx] = mean;
        d_bn2r[i*NF+f0+fx] = rsqrtf(var + EPSF);
    }
}

// ---------------- fc3: y[row] = relu(bn2(u[row])) . w3   (one warp per row)
__global__ void k_fc3(const float* __restrict__ g2, const float* __restrict__ bb2,
                      const float* __restrict__ w3){
    const int row  = blockIdx.x*8 + (threadIdx.x>>5);   // 512 blocks x 8 warps = 4096 rows
    const int lane = threadIdx.x & 31;
    const int i = row >> 9;
    const float* up = d_u + (size_t)row*NF;
    float s = 0.f;
    for (int f=lane; f<NF; f+=32){
        int gi = i*NF + f;
        float z = g2[gi]*(up[f]-d_bn2m[gi])*d_bn2r[gi] + bb2[gi];
        z = fmaxf(z, 0.f);
        s = fmaf(z, w3[gi], s);
    }
#pragma unroll
    for (int off=16; off; off>>=1) s += __shfl_xor_sync(0xffffffffu, s, off);
    if (lane==0) d_y[row] = s;
}

// ---------------- final: pair-sum, bn3 per layer, accumulate, labels
__global__ void k_final(const float* __restrict__ b3, const float* __restrict__ g3,
                        const float* __restrict__ bb3, const int* __restrict__ targets,
                        float* __restrict__ out, int out_size){
    const int qk = threadIdx.x;   // 256
    __shared__ double ss[256], sqs[256];
    float accum = 0.f;
    for (int i=0;i<NL;i++){
        float p = d_y[i*512 + 2*qk] + d_y[i*512 + 2*qk + 1] + 2.f*b3[i];
        ss[qk] = (double)p; sqs[qk] = (double)p*(double)p;
        __syncthreads();
        for (int off=128; off; off>>=1){
            if (qk<off){ ss[qk]+=ss[qk+off]; sqs[qk]+=sqs[qk+off]; }
            __syncthreads();
        }
        double mean = ss[0]/256.0;
        double var  = sqs[0]/256.0 - mean*mean;
        float rstd  = (float)rsqrt(var + 1e-5);
        accum += g3[i]*((p - (float)mean)*rstd) + bb3[i];
        __syncthreads();   // protect ss/sqs before next layer overwrites
    }
    out[qk] = accum;
    if (out_size >= 512){
        int qq = qk >> 4, kk = qk & 15;
        out[256 + qk] = (targets[qq]==targets[kk]) ? 1.f : 0.f;
    }
}

// ---------------- launcher ----------------
extern "C" void kernel_launch(void* const* d_in, const int* in_sizes, int n_in,
                              void* d_out, int out_size){
    const float* q_feat = (const float*)d_in[0];
    const float* g_feat = (const float*)d_in[1];
    const int*   targets= (const int*)  d_in[2];
    const float* se     = (const float*)d_in[3];
    const float* fc0w   = (const float*)d_in[4];
    const float* fc0b   = (const float*)d_in[5];
    const float* bn1g   = (const float*)d_in[6];
    const float* bn1b   = (const float*)d_in[7];
    const float* fc2w   = (const float*)d_in[8];
    const float* fc2b   = (const float*)d_in[9];
    const float* bn2g   = (const float*)d_in[10];
    const float* bn2b   = (const float*)d_in[11];
    const float* fc3w   = (const float*)d_in[12];
    const float* fc3b   = (const float*)d_in[13];
    const float* bn3g   = (const float*)d_in[14];
    const float* bn3b   = (const float*)d_in[15];
    float* out = (float*)d_out;

    uint32_t *p_qfp, *p_gfp, *p_w0p, *p_qryp, *p_keyp;
    cudaGetSymbolAddress((void**)&p_qfp,  d_qfp);
    cudaGetSymbolAddress((void**)&p_gfp,  d_gfp);
    cudaGetSymbolAddress((void**)&p_w0p,  d_w0p);
    cudaGetSymbolAddress((void**)&p_qryp, d_qryp);
    cudaGetSymbolAddress((void**)&p_keyp, d_keyp);

    const int nfeat = NB*NL*ND*NS;
    const int nw0   = NL*ND*ND;
    const int SCORE_SMEM = 4*NS*STR*4;   // 110592 B

    // context op (not stream-ordered, not captured, no allocation) — idempotent
    cudaFuncSetAttribute(k_score, cudaFuncAttributeMaxDynamicSharedMemorySize, SCORE_SMEM);

    k_sigse<<<(NL*NS*NS+255)/256, 256>>>(se);
    k_split<<<(nfeat+255)/256, 256>>>(q_feat, p_qfp, nfeat);
    k_split<<<(nfeat+255)/256, 256>>>(g_feat, p_gfp, nfeat);
    k_split<<<(nw0+255)/256,   256>>>(fc0w,   p_w0p, nw0);
    k_proj<<<dim3(8, NB, NL), 256>>>(p_qfp, fc0b, p_qryp);
    k_proj<<<dim3(8, NB, NL), 256>>>(p_gfp, fc0b, p_keyp);
    k_score<<<dim3(256, NL), 512, SCORE_SMEM>>>();
    k_bn1<<<NL, 512>>>();
    k_fc2<<<dim3(32, 8, NL), 256>>>(fc2w, fc2b, bn1g, bn1b);
    k_bn2<<<dim3(32, NL), 256>>>();
    k_fc3<<<512, 256>>>(bn2g, bn2b, fc3w);
    k_final<<<1, 256>>>(fc3b, bn3g, bn3b, targets, out, out_size);
}